// round 1
// baseline (speedup 1.0000x reference)
#include <cuda_runtime.h>
#include <math.h>

#define B   2
#define C   8
#define L   512
#define CH  256
#define CW  8
#define NH  8
#define DH  256
#define NTOT (B*L)            // 1024
#define FPC  (CH*CW)          // 2048 features per (n,c)
#define NCF  (NTOT*C*FPC)     // 16,777,216 elements per tensor
#define NROW (B*C*NH*L)       // 65536 attention rows
#define LL   (L*L)            // 262144

// ---- scratch (__device__ globals; no allocations allowed) ----
__device__ float g_conv0[NCF];
__device__ float g_conv1[NCF];
__device__ float g_conv2[NCF];
__device__ float g_q[NCF];
__device__ float g_k[NCF];
__device__ float g_v[NCF];
__device__ float g_a[NCF];
__device__ float g_rmax[NROW];
__device__ float g_rsum[NROW];

// ============================================================
// Kernel 1: fused 3x conv3x3 (pad 1), C=8 -> C=8, spatial 256x8.
// grid (1024, 4), block 256. Each block: one n, 64-row y tile.
// Each thread: 2 rows (yb, yb+32) x 1 col x (3 proj x 8 co) = 48 outputs.
// ============================================================
__global__ void conv3_kernel(const float* __restrict__ x,
                             const float* __restrict__ wq,
                             const float* __restrict__ wk,
                             const float* __restrict__ wv) {
    __shared__ float xt[8*66*10];   // [ci][66 rows][10 cols], zero padded
    __shared__ float wsm[3*576];    // [proj][co][ci][3][3]
    const int n  = blockIdx.x;
    const int y0 = blockIdx.y * 64;
    const int b  = n >> 9, l = n & 511;
    const int tid = threadIdx.x;

    for (int i = tid; i < 576; i += 256) {
        wsm[i]        = wq[i];
        wsm[576 + i]  = wk[i];
        wsm[1152 + i] = wv[i];
    }
    for (int i = tid; i < 8*66*10; i += 256) {
        int ci = i / 660, rem = i % 660;
        int yy = rem / 10, xx = rem % 10;
        int y = y0 + yy - 1, xc = xx - 1;
        float v = 0.f;
        if (y >= 0 && y < CH && xc >= 0 && xc < CW)
            v = x[(((size_t)(b*C + ci)*L + l)*CH + y)*CW + xc];
        xt[i] = v;
    }
    __syncthreads();

    const int yb = tid >> 3, w = tid & 7;
    float acc[2][24];
    #pragma unroll
    for (int r = 0; r < 2; r++)
        #pragma unroll
        for (int o = 0; o < 24; o++) acc[r][o] = 0.f;

    for (int ci = 0; ci < 8; ci++) {
        float xv[2][9];
        #pragma unroll
        for (int r = 0; r < 2; r++)
            #pragma unroll
            for (int ky = 0; ky < 3; ky++)
                #pragma unroll
                for (int kx = 0; kx < 3; kx++)
                    xv[r][ky*3 + kx] = xt[ci*660 + (yb + r*32 + ky)*10 + (w + kx)];
        #pragma unroll
        for (int o = 0; o < 24; o++) {
            int p = o >> 3, co = o & 7;
            const float* wp = &wsm[p*576 + (co*8 + ci)*9];
            #pragma unroll
            for (int k9 = 0; k9 < 9; k9++) {
                float ww = wp[k9];
                acc[0][o] += xv[0][k9] * ww;
                acc[1][o] += xv[1][k9] * ww;
            }
        }
    }
    #pragma unroll
    for (int p = 0; p < 3; p++) {
        float* op = (p == 0) ? g_conv0 : (p == 1) ? g_conv1 : g_conv2;
        #pragma unroll
        for (int co = 0; co < 8; co++)
            #pragma unroll
            for (int r = 0; r < 2; r++)
                op[(size_t)n*16384 + co*2048 + (size_t)(y0 + yb + r*32)*8 + w] = acc[r][p*8 + co];
    }
}

// ============================================================
// Kernel 2/5: per-channel linear  out[n,c,g,w] = sum_h A[n,c,h,w]*W[c,g,h]
// A layout: [n][c][h*8+w]  (n*16384 + c*2048 + h*8 + w)
// mode 0: out[n][c][g*8+w]     (q/k/v -> same layout)
// mode 1: out[b][c][l][g][w]   (final output tensor)
// grid (128, 4, 8): 8-n x 64-g x all-w tile, K=256 in 16-chunks. block 256.
// ============================================================
__global__ void mlin_kernel(const float* __restrict__ A, const float* __restrict__ W,
                            float* __restrict__ out, int mode) {
    __shared__ float As[64*17];   // [nw = n*8+w][k], pad 17
    __shared__ float Bs[64*16];   // [g][k]
    const int c  = blockIdx.z;
    const int n0 = blockIdx.x * 8;
    const int g0 = blockIdx.y * 64;
    const int tid = threadIdx.x;
    const int tg = tid >> 4, tnw = tid & 15;
    const float* Ab = A + (size_t)n0*16384 + c*2048;
    const float* Wb = W + (size_t)c*65536 + (size_t)g0*256;
    float acc[4][4] = {};

    for (int kc = 0; kc < 16; kc++) {
        #pragma unroll
        for (int ii = 0; ii < 4; ii++) {
            int i = tid + ii*256;
            int n = i >> 7, hw = i & 127, h = hw >> 3, w = hw & 7;
            As[(n*8 + w)*17 + h] = Ab[(size_t)n*16384 + (kc*16 + h)*8 + w];
            int g = i >> 4, k = i & 15;
            Bs[g*16 + k] = Wb[(size_t)g*256 + kc*16 + k];
        }
        __syncthreads();
        #pragma unroll
        for (int k = 0; k < 16; k++) {
            float av[4], bv[4];
            #pragma unroll
            for (int i = 0; i < 4; i++) av[i] = As[(tnw + 16*i)*17 + k];
            #pragma unroll
            for (int j = 0; j < 4; j++) bv[j] = Bs[(tg + 16*j)*16 + k];
            #pragma unroll
            for (int i = 0; i < 4; i++)
                #pragma unroll
                for (int j = 0; j < 4; j++) acc[i][j] += av[i] * bv[j];
        }
        __syncthreads();
    }
    #pragma unroll
    for (int i = 0; i < 4; i++) {
        int nw = tnw + 16*i;
        int n = n0 + (nw >> 3), w = nw & 7;
        #pragma unroll
        for (int j = 0; j < 4; j++) {
            int g = g0 + tg + 16*j;
            float v = acc[i][j];
            if (mode == 0) {
                out[(size_t)n*16384 + c*2048 + g*8 + w] = v;
            } else {
                int bb = n >> 9, ll = n & 511;
                out[((size_t)(bb*C + c)*L + ll)*2048 + g*8 + w] = v;
            }
        }
    }
}

// ============================================================
// Kernel 3: RoPE on first 32 dims of q and k (pairs 2j,2j+1, j<16).
// grid 4096, block 256 — exactly B*L*C*NH*16 threads.
// ============================================================
__global__ void rope_kernel() {
    int t = blockIdx.x * 256 + threadIdx.x;
    int j  = t & 15;  t >>= 4;
    int nh = t & 7;   t >>= 3;
    int c  = t & 7;   t >>= 3;
    int l  = t & 511; t >>= 9;
    int b  = t;
    size_t base = (size_t)(b*L + l)*16384 + c*2048 + nh*256 + 2*j;
    float invf = powf(10000.f, -(float)j / 16.f);
    float sn, cs;
    sincosf((float)l * invf, &sn, &cs);
    float q0 = g_q[base], q1 = g_q[base + 1];
    g_q[base]     = q0*cs - q1*sn;
    g_q[base + 1] = q1*cs + q0*sn;
    float k0 = g_k[base], k1 = g_k[base + 1];
    g_k[base]     = k0*cs - k1*sn;
    g_k[base + 1] = k1*cs + k0*sn;
}

// ============================================================
// Kernel 4a: qk[z,l,m] = (q[l,:].k[m,:])/16 + prev_qk.  z = (b*C+c)*NH+nh.
// grid (8 m-tiles, 8 l-tiles, 128), block 256. 64x64x256.
// ============================================================
__global__ void qk_kernel(const float* __restrict__ prev, float* __restrict__ qk) {
    __shared__ float Qs[64*17];
    __shared__ float Ks[64*17];
    const int z = blockIdx.z;
    const int b = z >> 6, c = (z >> 3) & 7, nh = z & 7;
    const int l0 = blockIdx.y * 64, m0 = blockIdx.x * 64;
    const float* qb = g_q + (size_t)b*L*16384 + c*2048 + nh*256;
    const float* kb = g_k + (size_t)b*L*16384 + c*2048 + nh*256;
    const int tid = threadIdx.x;
    const int tl = tid >> 4, tm = tid & 15;
    float acc[4][4] = {};

    for (int kc = 0; kc < 16; kc++) {
        #pragma unroll
        for (int ii = 0; ii < 4; ii++) {
            int i = tid + ii*256;
            int r = i >> 4, kk = i & 15;
            Qs[r*17 + kk] = qb[(size_t)(l0 + r)*16384 + kc*16 + kk];
            Ks[r*17 + kk] = kb[(size_t)(m0 + r)*16384 + kc*16 + kk];
        }
        __syncthreads();
        #pragma unroll
        for (int k = 0; k < 16; k++) {
            float av[4], bv[4];
            #pragma unroll
            for (int i = 0; i < 4; i++) av[i] = Qs[(tl + 16*i)*17 + k];
            #pragma unroll
            for (int j = 0; j < 4; j++) bv[j] = Ks[(tm + 16*j)*17 + k];
            #pragma unroll
            for (int i = 0; i < 4; i++)
                #pragma unroll
                for (int j = 0; j < 4; j++) acc[i][j] += av[i] * bv[j];
        }
        __syncthreads();
    }
    #pragma unroll
    for (int i = 0; i < 4; i++) {
        int l = l0 + tl + 16*i;
        #pragma unroll
        for (int j = 0; j < 4; j++) {
            int m = m0 + tm + 16*j;
            size_t idx = (size_t)z*LL + (size_t)l*512 + m;
            qk[idx] = acc[i][j] * 0.0625f + prev[idx];
        }
    }
}

// ============================================================
// Kernel 4b: per-row max + sumexp. grid 65536, block 128 (float4 each).
// ============================================================
__global__ void stats_kernel(const float* __restrict__ qk) {
    const int row = blockIdx.x;
    const int tid = threadIdx.x;
    const float4 v = reinterpret_cast<const float4*>(qk + (size_t)row*512)[tid];
    float mx = fmaxf(fmaxf(v.x, v.y), fmaxf(v.z, v.w));
    #pragma unroll
    for (int o = 16; o; o >>= 1) mx = fmaxf(mx, __shfl_xor_sync(~0u, mx, o));
    __shared__ float sm[4], ss[4];
    if ((tid & 31) == 0) sm[tid >> 5] = mx;
    __syncthreads();
    mx = fmaxf(fmaxf(sm[0], sm[1]), fmaxf(sm[2], sm[3]));
    float s = expf(v.x - mx) + expf(v.y - mx) + expf(v.z - mx) + expf(v.w - mx);
    #pragma unroll
    for (int o = 16; o; o >>= 1) s += __shfl_xor_sync(~0u, s, o);
    if ((tid & 31) == 0) ss[tid >> 5] = s;
    __syncthreads();
    if (tid == 0) {
        g_rmax[row] = mx;
        g_rsum[row] = ss[0] + ss[1] + ss[2] + ss[3];
    }
}

// ============================================================
// Kernel 4c: a[l,d] = sum_m softmax(qk)[l,m] * v[m,d], exp on the fly.
// Stores straight into the [n][c][f] layout the wo GEMM consumes.
// grid (4 d-tiles, 8 l-tiles, 128), block 256. 64x64x512.
// ============================================================
__global__ void pv_kernel(const float* __restrict__ qk) {
    __shared__ float Ps[64*17];
    __shared__ float Vs[16*64];
    __shared__ float rmx[64];
    const int z = blockIdx.z;
    const int b = z >> 6, c = (z >> 3) & 7, nh = z & 7;
    const int l0 = blockIdx.y * 64, d0 = blockIdx.x * 64;
    const float* vb  = g_v + (size_t)b*L*16384 + c*2048 + nh*256;
    const float* qkb = qk + (size_t)z*LL;
    const int tid = threadIdx.x;
    if (tid < 64) rmx[tid] = g_rmax[z*512 + l0 + tid];
    __syncthreads();
    const int tl = tid >> 4, td = tid & 15;
    float acc[4][4] = {};

    for (int kc = 0; kc < 32; kc++) {
        #pragma unroll
        for (int ii = 0; ii < 4; ii++) {
            int i = tid + ii*256;
            int r = i >> 4, mm = i & 15;
            Ps[r*17 + mm] = expf(qkb[(size_t)(l0 + r)*512 + kc*16 + mm] - rmx[r]);
            int m2 = i >> 6, dd = i & 63;
            Vs[m2*64 + dd] = vb[(size_t)(kc*16 + m2)*16384 + d0 + dd];
        }
        __syncthreads();
        #pragma unroll
        for (int k = 0; k < 16; k++) {
            float av[4], bv[4];
            #pragma unroll
            for (int i = 0; i < 4; i++) av[i] = Ps[(tl + 16*i)*17 + k];
            #pragma unroll
            for (int j = 0; j < 4; j++) bv[j] = Vs[k*64 + td + 16*j];
            #pragma unroll
            for (int i = 0; i < 4; i++)
                #pragma unroll
                for (int j = 0; j < 4; j++) acc[i][j] += av[i] * bv[j];
        }
        __syncthreads();
    }
    #pragma unroll
    for (int i = 0; i < 4; i++) {
        int l = l0 + tl + 16*i;
        float inv = 1.f / g_rsum[z*512 + l];
        #pragma unroll
        for (int j = 0; j < 4; j++) {
            int d = d0 + td + 16*j;
            g_a[(size_t)(b*L + l)*16384 + c*2048 + nh*256 + d] = acc[i][j] * inv;
        }
    }
}

// ============================================================
extern "C" void kernel_launch(void* const* d_in, const int* in_sizes, int n_in,
                              void* d_out, int out_size) {
    const float* x    = (const float*)d_in[0];
    const float* prev = (const float*)d_in[1];
    const float* cw_q = (const float*)d_in[2];
    const float* cw_k = (const float*)d_in[3];
    const float* cw_v = (const float*)d_in[4];
    const float* wq   = (const float*)d_in[5];
    const float* wk   = (const float*)d_in[6];
    const float* wv   = (const float*)d_in[7];
    const float* wo   = (const float*)d_in[8];
    float* out    = (float*)d_out;
    float* qk_out = out + (size_t)NCF;   // qk tensor follows out tensor

    float *p_c0, *p_c1, *p_c2, *p_q, *p_k, *p_v, *p_a;
    cudaGetSymbolAddress((void**)&p_c0, g_conv0);
    cudaGetSymbolAddress((void**)&p_c1, g_conv1);
    cudaGetSymbolAddress((void**)&p_c2, g_conv2);
    cudaGetSymbolAddress((void**)&p_q,  g_q);
    cudaGetSymbolAddress((void**)&p_k,  g_k);
    cudaGetSymbolAddress((void**)&p_v,  g_v);
    cudaGetSymbolAddress((void**)&p_a,  g_a);

    conv3_kernel<<<dim3(1024, 4), 256>>>(x, cw_q, cw_k, cw_v);
    mlin_kernel<<<dim3(128, 4, 8), 256>>>(p_c0, wq, p_q, 0);
    mlin_kernel<<<dim3(128, 4, 8), 256>>>(p_c1, wk, p_k, 0);
    mlin_kernel<<<dim3(128, 4, 8), 256>>>(p_c2, wv, p_v, 0);
    rope_kernel<<<4096, 256>>>();
    qk_kernel<<<dim3(8, 8, 128), 256>>>(prev, qk_out);
    stats_kernel<<<65536, 128>>>(qk_out);
    pv_kernel<<<dim3(4, 8, 128), 256>>>(qk_out);
    mlin_kernel<<<dim3(128, 4, 8), 256>>>(p_a, wo, out, 1);
}

// round 3
// speedup vs baseline: 1.6077x; 1.6077x over previous
#include <cuda_runtime.h>
#include <cuda_bf16.h>
#include <mma.h>
#include <math.h>
#include <cstdint>

using namespace nvcuda;

#define B   2
#define C   8
#define L   512
#define NTOT (B*L)            // 1024
#define NCF  (NTOT*C*2048)    // 16,777,216
#define NROW (B*C*NH*L)
#define NH  8
#define LL  (L*L)             // 262144

// ---- scratch (validated round-1 layouts) ----
__device__ float g_conv0[NCF];
__device__ float g_conv1[NCF];
__device__ float g_conv2[NCF];
__device__ float g_q[NCF];      // [n][c][f], f = nh*256 + d (= h*8+w)
__device__ float g_k[NCF];
__device__ float g_v[NCF];
__device__ float g_a[NCF];
__device__ float g_rmax[B*C*NH*L];
__device__ float g_rsum[B*C*NH*L];

// ---- smem plan (dynamic) ----
// operands: Ah[128][40] Al Bh Bl bf16 (10240 B each) = 40960
// epilogue: Cs float[128][128] = 65536 (aliases operands)
// pv extras: rmx at 65536, rinv at 66048
#define SM_AH 0
#define SM_AL 10240
#define SM_BH 20480
#define SM_BL 30720
#define SM_RMX 65536
#define SM_RINV 66048
#define SMEM_BYTES 66560

__device__ __forceinline__ void bsplit(float x, __nv_bfloat16& h, __nv_bfloat16& l) {
    h = __float2bfloat16(x);
    l = __float2bfloat16(x - __bfloat162float(h));
}
__device__ __forceinline__ void split_store(__nv_bfloat16* Hb, __nv_bfloat16* Lb,
                                            int idx, float v) {
    __nv_bfloat16 h, l;
    bsplit(v, h, l);
    Hb[idx] = h; Lb[idx] = l;
}

typedef wmma::fragment<wmma::accumulator, 16, 16, 16, float> AccFrag;

// B stored [n rows][k cols] row-major => K x N col_major fragment, ldm 40
__device__ __forceinline__ void mma_chunk_colB(
    const __nv_bfloat16* Ah, const __nv_bfloat16* Al,
    const __nv_bfloat16* Bh, const __nv_bfloat16* Bl,
    int warp_m, int warp_n, AccFrag (&acc)[4][2])
{
    #pragma unroll
    for (int ks = 0; ks < 2; ks++) {
        wmma::fragment<wmma::matrix_b, 16, 16, 16, __nv_bfloat16, wmma::col_major> bh[2], bl[2];
        #pragma unroll
        for (int j = 0; j < 2; j++) {
            int n_off = warp_n * 32 + j * 16;
            wmma::load_matrix_sync(bh[j], Bh + n_off * 40 + ks * 16, 40);
            wmma::load_matrix_sync(bl[j], Bl + n_off * 40 + ks * 16, 40);
        }
        #pragma unroll
        for (int i = 0; i < 4; i++) {
            int m_off = warp_m * 64 + i * 16;
            wmma::fragment<wmma::matrix_a, 16, 16, 16, __nv_bfloat16, wmma::row_major> ah, al;
            wmma::load_matrix_sync(ah, Ah + m_off * 40 + ks * 16, 40);
            wmma::load_matrix_sync(al, Al + m_off * 40 + ks * 16, 40);
            #pragma unroll
            for (int j = 0; j < 2; j++) {
                wmma::mma_sync(acc[i][j], ah, bh[j], acc[i][j]);
                wmma::mma_sync(acc[i][j], al, bh[j], acc[i][j]);
                wmma::mma_sync(acc[i][j], ah, bl[j], acc[i][j]);
            }
        }
    }
}

// B stored [k rows][n cols] row-major (K x N row_major), ldm 136 (pv)
__device__ __forceinline__ void mma_chunk_rowB(
    const __nv_bfloat16* Ah, const __nv_bfloat16* Al,
    const __nv_bfloat16* Bh, const __nv_bfloat16* Bl,
    int warp_m, int warp_n, AccFrag (&acc)[4][2])
{
    #pragma unroll
    for (int ks = 0; ks < 2; ks++) {
        wmma::fragment<wmma::matrix_b, 16, 16, 16, __nv_bfloat16, wmma::row_major> bh[2], bl[2];
        #pragma unroll
        for (int j = 0; j < 2; j++) {
            int n_off = warp_n * 32 + j * 16;
            wmma::load_matrix_sync(bh[j], Bh + (ks * 16) * 136 + n_off, 136);
            wmma::load_matrix_sync(bl[j], Bl + (ks * 16) * 136 + n_off, 136);
        }
        #pragma unroll
        for (int i = 0; i < 4; i++) {
            int m_off = warp_m * 64 + i * 16;
            wmma::fragment<wmma::matrix_a, 16, 16, 16, __nv_bfloat16, wmma::row_major> ah, al;
            wmma::load_matrix_sync(ah, Ah + m_off * 40 + ks * 16, 40);
            wmma::load_matrix_sync(al, Al + m_off * 40 + ks * 16, 40);
            #pragma unroll
            for (int j = 0; j < 2; j++) {
                wmma::mma_sync(acc[i][j], ah, bh[j], acc[i][j]);
                wmma::mma_sync(acc[i][j], al, bh[j], acc[i][j]);
                wmma::mma_sync(acc[i][j], ah, bl[j], acc[i][j]);
            }
        }
    }
}

#define EPILOGUE_STORE() \
    __syncthreads(); \
    { \
        float* Cs = (float*)smem; \
        wmma::store_matrix_sync(Cs + (warp_m * 64) * 128 + warp_n * 32, acc[0][0], 128, wmma::mem_row_major); \
        wmma::store_matrix_sync(Cs + (warp_m * 64) * 128 + warp_n * 32 + 16, acc[0][1], 128, wmma::mem_row_major); \
        wmma::store_matrix_sync(Cs + (warp_m * 64 + 16) * 128 + warp_n * 32, acc[1][0], 128, wmma::mem_row_major); \
        wmma::store_matrix_sync(Cs + (warp_m * 64 + 16) * 128 + warp_n * 32 + 16, acc[1][1], 128, wmma::mem_row_major); \
        wmma::store_matrix_sync(Cs + (warp_m * 64 + 32) * 128 + warp_n * 32, acc[2][0], 128, wmma::mem_row_major); \
        wmma::store_matrix_sync(Cs + (warp_m * 64 + 32) * 128 + warp_n * 32 + 16, acc[2][1], 128, wmma::mem_row_major); \
        wmma::store_matrix_sync(Cs + (warp_m * 64 + 48) * 128 + warp_n * 32, acc[3][0], 128, wmma::mem_row_major); \
        wmma::store_matrix_sync(Cs + (warp_m * 64 + 48) * 128 + warp_n * 32 + 16, acc[3][1], 128, wmma::mem_row_major); \
    } \
    __syncthreads();

// ============================================================
// mlin_wm: out[(n,w), g] = sum_h A[n][c][h*8+w] * W[c][g][h]
// grid (64, 2, 8), block 256.  mode 0: q/k/v layout; mode 1: final out.
// ============================================================
__global__ void __launch_bounds__(256)
mlin_wm(const float* __restrict__ A, const float* __restrict__ W,
        float* __restrict__ out, int mode) {
    extern __shared__ char smem[];
    __nv_bfloat16* Ah = (__nv_bfloat16*)(smem + SM_AH);
    __nv_bfloat16* Al = (__nv_bfloat16*)(smem + SM_AL);
    __nv_bfloat16* Bh = (__nv_bfloat16*)(smem + SM_BH);
    __nv_bfloat16* Bl = (__nv_bfloat16*)(smem + SM_BL);
    const int tid = threadIdx.x;
    const int warp_m = (tid >> 5) >> 2, warp_n = (tid >> 5) & 3;
    const int c = blockIdx.z, m0 = blockIdx.x * 128, g0 = blockIdx.y * 128;

    AccFrag acc[4][2];
    #pragma unroll
    for (int i = 0; i < 4; i++)
        #pragma unroll
        for (int j = 0; j < 2; j++) wmma::fill_fragment(acc[i][j], 0.0f);

    for (int kc = 0; kc < 8; kc++) {
        const int h0 = kc * 32;
        const float* Abase = A + (size_t)(m0 >> 3) * 16384 + c * 2048 + h0 * 8;
        const float* Wb = W + (size_t)c * 65536 + (size_t)g0 * 256 + h0;
        #pragma unroll
        for (int it = 0; it < 4; it++) {
            int idx = tid + it * 256;
            // A: 16 n-blocks x 256 contiguous floats
            {
                int n_l = idx >> 6, p4 = idx & 63;
                float4 v = *(const float4*)(Abase + (size_t)n_l * 16384 + p4 * 4);
                int p = p4 * 4, h_rel = p >> 3, w0 = p & 7;
                int rb = n_l * 8 + w0;
                split_store(Ah, Al, (rb + 0) * 40 + h_rel, v.x);
                split_store(Ah, Al, (rb + 1) * 40 + h_rel, v.y);
                split_store(Ah, Al, (rb + 2) * 40 + h_rel, v.z);
                split_store(Ah, Al, (rb + 3) * 40 + h_rel, v.w);
            }
            // B: 128 g-rows x 8 float4 along h
            {
                int g_l = idx >> 3, h4 = idx & 7;
                float4 v = *(const float4*)(Wb + (size_t)g_l * 256 + h4 * 4);
                int cb = g_l * 40 + h4 * 4;
                split_store(Bh, Bl, cb + 0, v.x);
                split_store(Bh, Bl, cb + 1, v.y);
                split_store(Bh, Bl, cb + 2, v.z);
                split_store(Bh, Bl, cb + 3, v.w);
            }
        }
        __syncthreads();
        mma_chunk_colB(Ah, Al, Bh, Bl, warp_m, warp_n, acc);
        __syncthreads();
    }

    EPILOGUE_STORE();
    const float* Cs = (const float*)smem;
    const int col = tid & 127;
    for (int jj = 0; jj < 64; jj++) {
        int r = jj * 2 + (tid >> 7);
        float v = Cs[r * 128 + col];
        int n = (m0 + r) >> 3, w = r & 7, g = g0 + col;
        if (mode == 0) {
            out[(size_t)n * 16384 + c * 2048 + g * 8 + w] = v;
        } else {
            int b = n >> 9, l = n & 511;
            out[((size_t)(b * 8 + c) * 512 + l) * 2048 + g * 8 + w] = v;
        }
    }
}

// ============================================================
// qk_wm: qk[z,l,m] = (q[l,:].k[m,:])/16 + prev.  grid (4, 4, 128), block 256.
// ============================================================
__global__ void __launch_bounds__(256)
qk_wm(const float* __restrict__ prev, float* __restrict__ qk) {
    extern __shared__ char smem[];
    __nv_bfloat16* Ah = (__nv_bfloat16*)(smem + SM_AH);
    __nv_bfloat16* Al = (__nv_bfloat16*)(smem + SM_AL);
    __nv_bfloat16* Bh = (__nv_bfloat16*)(smem + SM_BH);
    __nv_bfloat16* Bl = (__nv_bfloat16*)(smem + SM_BL);
    const int tid = threadIdx.x;
    const int warp_m = (tid >> 5) >> 2, warp_n = (tid >> 5) & 3;
    const int z = blockIdx.z;
    const int b = z >> 6, c = (z >> 3) & 7, nh = z & 7;
    const int l0 = blockIdx.y * 128, m0 = blockIdx.x * 128;
    const float* qb = g_q + (size_t)b * 512 * 16384 + c * 2048 + nh * 256;
    const float* kb = g_k + (size_t)b * 512 * 16384 + c * 2048 + nh * 256;

    AccFrag acc[4][2];
    #pragma unroll
    for (int i = 0; i < 4; i++)
        #pragma unroll
        for (int j = 0; j < 2; j++) wmma::fill_fragment(acc[i][j], 0.0f);

    for (int kc = 0; kc < 8; kc++) {
        const int k0 = kc * 32;
        #pragma unroll
        for (int it = 0; it < 4; it++) {
            int idx = tid + it * 256;
            int r = idx >> 3, d4 = idx & 7;
            float4 va = *(const float4*)(qb + (size_t)(l0 + r) * 16384 + k0 + d4 * 4);
            float4 vb = *(const float4*)(kb + (size_t)(m0 + r) * 16384 + k0 + d4 * 4);
            int cb = r * 40 + d4 * 4;
            split_store(Ah, Al, cb + 0, va.x);
            split_store(Ah, Al, cb + 1, va.y);
            split_store(Ah, Al, cb + 2, va.z);
            split_store(Ah, Al, cb + 3, va.w);
            split_store(Bh, Bl, cb + 0, vb.x);
            split_store(Bh, Bl, cb + 1, vb.y);
            split_store(Bh, Bl, cb + 2, vb.z);
            split_store(Bh, Bl, cb + 3, vb.w);
        }
        __syncthreads();
        mma_chunk_colB(Ah, Al, Bh, Bl, warp_m, warp_n, acc);
        __syncthreads();
    }

    EPILOGUE_STORE();
    const float* Cs = (const float*)smem;
    const int col = tid & 127;
    for (int jj = 0; jj < 64; jj++) {
        int r = jj * 2 + (tid >> 7);
        size_t idx = (size_t)z * LL + (size_t)(l0 + r) * 512 + m0 + col;
        qk[idx] = Cs[r * 128 + col] * 0.0625f + prev[idx];
    }
}

// ============================================================
// pv_wm: a[l,d] = sum_m exp(qk[l,m]-rmax[l]) * V[m,d] / rsum[l]
// grid (2, 4, 128), block 256. K=512 -> 16 chunks.
// ============================================================
__global__ void __launch_bounds__(256)
pv_wm(const float* __restrict__ qkv) {
    extern __shared__ char smem[];
    __nv_bfloat16* Ah = (__nv_bfloat16*)(smem + SM_AH);
    __nv_bfloat16* Al = (__nv_bfloat16*)(smem + SM_AL);
    __nv_bfloat16* Bh = (__nv_bfloat16*)(smem + SM_BH);
    __nv_bfloat16* Bl = (__nv_bfloat16*)(smem + SM_BL);
    float* rmx  = (float*)(smem + SM_RMX);
    float* rinv = (float*)(smem + SM_RINV);
    const int tid = threadIdx.x;
    const int warp_m = (tid >> 5) >> 2, warp_n = (tid >> 5) & 3;
    const int z = blockIdx.z;
    const int b = z >> 6, c = (z >> 3) & 7, nh = z & 7;
    const int l0 = blockIdx.y * 128, d0 = blockIdx.x * 128;
    const float* vb = g_v + (size_t)b * 512 * 16384 + c * 2048 + nh * 256;

    if (tid < 128) {
        rmx[tid]  = g_rmax[z * 512 + l0 + tid];
        rinv[tid] = 1.0f / g_rsum[z * 512 + l0 + tid];
    }
    __syncthreads();

    AccFrag acc[4][2];
    #pragma unroll
    for (int i = 0; i < 4; i++)
        #pragma unroll
        for (int j = 0; j < 2; j++) wmma::fill_fragment(acc[i][j], 0.0f);

    for (int kc = 0; kc < 16; kc++) {
        const int k0 = kc * 32;
        #pragma unroll
        for (int it = 0; it < 4; it++) {
            int idx = tid + it * 256;
            // A: P = exp(qk - rmax), rows l, k = m
            {
                int r = idx >> 3, d4 = idx & 7;
                float4 v = *(const float4*)(qkv + (size_t)z * LL + (size_t)(l0 + r) * 512 + k0 + d4 * 4);
                float mx = rmx[r];
                v.x = __expf(v.x - mx); v.y = __expf(v.y - mx);
                v.z = __expf(v.z - mx); v.w = __expf(v.w - mx);
                int cb = r * 40 + d4 * 4;
                split_store(Ah, Al, cb + 0, v.x);
                split_store(Ah, Al, cb + 1, v.y);
                split_store(Ah, Al, cb + 2, v.z);
                split_store(Ah, Al, cb + 3, v.w);
            }
            // B: V rows = k (m), cols d -> [32][136] row-major K x N
            {
                int m_l = idx >> 5, d4 = idx & 31;
                float4 v = *(const float4*)(vb + (size_t)(k0 + m_l) * 16384 + d0 + d4 * 4);
                int cb = m_l * 136 + d4 * 4;
                split_store(Bh, Bl, cb + 0, v.x);
                split_store(Bh, Bl, cb + 1, v.y);
                split_store(Bh, Bl, cb + 2, v.z);
                split_store(Bh, Bl, cb + 3, v.w);
            }
        }
        __syncthreads();
        mma_chunk_rowB(Ah, Al, Bh, Bl, warp_m, warp_n, acc);
        __syncthreads();
    }

    // rinv/rmx live above 64KB staging; safe through epilogue
    EPILOGUE_STORE();
    const float* Cs = (const float*)smem;
    const int col = tid & 127;
    for (int jj = 0; jj < 64; jj++) {
        int r = jj * 2 + (tid >> 7);
        int l = l0 + r;
        float v = Cs[r * 128 + col] * rinv[r];
        int f = nh * 256 + d0 + col;
        g_a[(size_t)(b * 512 + l) * 16384 + c * 2048 + f] = v;
    }
}

// ============================================================
// conv3 / rope / stats: validated round-1 versions
// ============================================================
__global__ void conv3_kernel(const float* __restrict__ x,
                             const float* __restrict__ wq,
                             const float* __restrict__ wk,
                             const float* __restrict__ wv) {
    __shared__ float xt[8*66*10];
    __shared__ float wsm[3*576];
    const int n  = blockIdx.x;
    const int y0 = blockIdx.y * 64;
    const int b  = n >> 9, l = n & 511;
    const int tid = threadIdx.x;

    for (int i = tid; i < 576; i += 256) {
        wsm[i] = wq[i]; wsm[576 + i] = wk[i]; wsm[1152 + i] = wv[i];
    }
    for (int i = tid; i < 8*66*10; i += 256) {
        int ci = i / 660, rem = i % 660;
        int yy = rem / 10, xx = rem % 10;
        int y = y0 + yy - 1, xc = xx - 1;
        float v = 0.f;
        if (y >= 0 && y < 256 && xc >= 0 && xc < 8)
            v = x[(((size_t)(b*C + ci)*L + l)*256 + y)*8 + xc];
        xt[i] = v;
    }
    __syncthreads();

    const int yb = tid >> 3, w = tid & 7;
    float acc[2][24];
    #pragma unroll
    for (int r = 0; r < 2; r++)
        #pragma unroll
        for (int o = 0; o < 24; o++) acc[r][o] = 0.f;

    for (int ci = 0; ci < 8; ci++) {
        float xv[2][9];
        #pragma unroll
        for (int r = 0; r < 2; r++)
            #pragma unroll
            for (int ky = 0; ky < 3; ky++)
                #pragma unroll
                for (int kx = 0; kx < 3; kx++)
                    xv[r][ky*3 + kx] = xt[ci*660 + (yb + r*32 + ky)*10 + (w + kx)];
        #pragma unroll
        for (int o = 0; o < 24; o++) {
            int p = o >> 3, co = o & 7;
            const float* wp = &wsm[p*576 + (co*8 + ci)*9];
            #pragma unroll
            for (int k9 = 0; k9 < 9; k9++) {
                float ww = wp[k9];
                acc[0][o] += xv[0][k9] * ww;
                acc[1][o] += xv[1][k9] * ww;
            }
        }
    }
    #pragma unroll
    for (int p = 0; p < 3; p++) {
        float* op = (p == 0) ? g_conv0 : (p == 1) ? g_conv1 : g_conv2;
        #pragma unroll
        for (int co = 0; co < 8; co++)
            #pragma unroll
            for (int r = 0; r < 2; r++)
                op[(size_t)n*16384 + co*2048 + (size_t)(y0 + yb + r*32)*8 + w] = acc[r][p*8 + co];
    }
}

__global__ void rope_kernel() {
    int t = blockIdx.x * 256 + threadIdx.x;
    int j  = t & 15;  t >>= 4;
    int nh = t & 7;   t >>= 3;
    int c  = t & 7;   t >>= 3;
    int l  = t & 511; t >>= 9;
    int b  = t;
    size_t base = (size_t)(b*L + l)*16384 + c*2048 + nh*256 + 2*j;
    float invf = powf(10000.f, -(float)j / 16.f);
    float sn, cs;
    sincosf((float)l * invf, &sn, &cs);
    float q0 = g_q[base], q1 = g_q[base + 1];
    g_q[base]     = q0*cs - q1*sn;
    g_q[base + 1] = q1*cs + q0*sn;
    float k0 = g_k[base], k1 = g_k[base + 1];
    g_k[base]     = k0*cs - k1*sn;
    g_k[base + 1] = k1*cs + k0*sn;
}

__global__ void stats_kernel(const float* __restrict__ qk) {
    const int row = blockIdx.x;
    const int tid = threadIdx.x;
    const float4 v = reinterpret_cast<const float4*>(qk + (size_t)row*512)[tid];
    float mx = fmaxf(fmaxf(v.x, v.y), fmaxf(v.z, v.w));
    #pragma unroll
    for (int o = 16; o; o >>= 1) mx = fmaxf(mx, __shfl_xor_sync(~0u, mx, o));
    __shared__ float sm[4], ss[4];
    if ((tid & 31) == 0) sm[tid >> 5] = mx;
    __syncthreads();
    mx = fmaxf(fmaxf(sm[0], sm[1]), fmaxf(sm[2], sm[3]));
    float s = expf(v.x - mx) + expf(v.y - mx) + expf(v.z - mx) + expf(v.w - mx);
    #pragma unroll
    for (int o = 16; o; o >>= 1) s += __shfl_xor_sync(~0u, s, o);
    if ((tid & 31) == 0) ss[tid >> 5] = s;
    __syncthreads();
    if (tid == 0) {
        g_rmax[row] = mx;
        g_rsum[row] = ss[0] + ss[1] + ss[2] + ss[3];
    }
}

// ============================================================
extern "C" void kernel_launch(void* const* d_in, const int* in_sizes, int n_in,
                              void* d_out, int out_size) {
    const float* x    = (const float*)d_in[0];
    const float* prev = (const float*)d_in[1];
    const float* cw_q = (const float*)d_in[2];
    const float* cw_k = (const float*)d_in[3];
    const float* cw_v = (const float*)d_in[4];
    const float* wq   = (const float*)d_in[5];
    const float* wk   = (const float*)d_in[6];
    const float* wv   = (const float*)d_in[7];
    const float* wo   = (const float*)d_in[8];
    float* out    = (float*)d_out;
    float* qk_out = out + (size_t)NCF;

    float *p_c0, *p_c1, *p_c2, *p_q, *p_k, *p_v, *p_a;
    cudaGetSymbolAddress((void**)&p_c0, g_conv0);
    cudaGetSymbolAddress((void**)&p_c1, g_conv1);
    cudaGetSymbolAddress((void**)&p_c2, g_conv2);
    cudaGetSymbolAddress((void**)&p_q,  g_q);
    cudaGetSymbolAddress((void**)&p_k,  g_k);
    cudaGetSymbolAddress((void**)&p_v,  g_v);
    cudaGetSymbolAddress((void**)&p_a,  g_a);

    cudaFuncSetAttribute(mlin_wm, cudaFuncAttributeMaxDynamicSharedMemorySize, SMEM_BYTES);
    cudaFuncSetAttribute(qk_wm,   cudaFuncAttributeMaxDynamicSharedMemorySize, SMEM_BYTES);
    cudaFuncSetAttribute(pv_wm,   cudaFuncAttributeMaxDynamicSharedMemorySize, SMEM_BYTES);

    conv3_kernel<<<dim3(1024, 4), 256>>>(x, cw_q, cw_k, cw_v);
    mlin_wm<<<dim3(64, 2, 8), 256, SMEM_BYTES>>>(p_c0, wq, p_q, 0);
    mlin_wm<<<dim3(64, 2, 8), 256, SMEM_BYTES>>>(p_c1, wk, p_k, 0);
    mlin_wm<<<dim3(64, 2, 8), 256, SMEM_BYTES>>>(p_c2, wv, p_v, 0);
    rope_kernel<<<4096, 256>>>();
    qk_wm<<<dim3(4, 4, 128), 256, SMEM_BYTES>>>(prev, qk_out);
    stats_kernel<<<65536, 128>>>(qk_out);
    pv_wm<<<dim3(2, 4, 128), 256, SMEM_BYTES>>>(qk_out);
    mlin_wm<<<dim3(64, 2, 8), 256, SMEM_BYTES>>>(p_a, wo, out, 1);
}

// round 4
// speedup vs baseline: 1.7912x; 1.1141x over previous
#include <cuda_runtime.h>
#include <cuda_bf16.h>
#include <mma.h>
#include <math.h>
#include <cstdint>

using namespace nvcuda;

#define B   2
#define C   8
#define L   512
#define NTOT (B*L)
#define NCF  (NTOT*C*2048)    // 16,777,216
#define NH  8
#define LL  (L*L)

// ---- scratch ----
__device__ float g_conv0[NCF];
__device__ float g_conv1[NCF];
__device__ float g_conv2[NCF];
__device__ float g_q[NCF];      // [n][c][f]
__device__ float g_k[NCF];
__device__ float g_v[NCF];
__device__ float g_a[NCF];
__device__ float g_rmax[B*C*NH*L];
__device__ float g_rsum[B*C*NH*L];

// ---- smem plan: double-buffered operands + aliased f32 epilogue tile ----
// buffer p at p*40960: Ah(10240) Al Bh Bl ; epilogue Cs f32[128][128]=65536 aliases
#define BUF_STRIDE 40960
#define OFF_AL 10240
#define OFF_BH 20480
#define OFF_BL 30720
#define SM_RMX 81920
#define SM_RINV 82432
#define SMEM_BYTES 82944

__device__ __forceinline__ void bsplit(float x, __nv_bfloat16& h, __nv_bfloat16& l) {
    h = __float2bfloat16(x);
    l = __float2bfloat16(x - __bfloat162float(h));
}
__device__ __forceinline__ void split_store(__nv_bfloat16* Hb, __nv_bfloat16* Lb,
                                            int idx, float v) {
    __nv_bfloat16 h, l;
    bsplit(v, h, l);
    Hb[idx] = h; Lb[idx] = l;
}

typedef wmma::fragment<wmma::accumulator, 16, 16, 16, float> AccFrag;

// B in smem as [n rows][k cols] (K-major rows) => col_major K x N frag, ldm 40
__device__ __forceinline__ void mma_chunk_colB(
    const char* buf, int warp_m, int warp_n, AccFrag (&acc)[4][2])
{
    const __nv_bfloat16* Ah = (const __nv_bfloat16*)(buf);
    const __nv_bfloat16* Al = (const __nv_bfloat16*)(buf + OFF_AL);
    const __nv_bfloat16* Bh = (const __nv_bfloat16*)(buf + OFF_BH);
    const __nv_bfloat16* Bl = (const __nv_bfloat16*)(buf + OFF_BL);
    #pragma unroll
    for (int ks = 0; ks < 2; ks++) {
        wmma::fragment<wmma::matrix_b, 16, 16, 16, __nv_bfloat16, wmma::col_major> bh[2], bl[2];
        #pragma unroll
        for (int j = 0; j < 2; j++) {
            int n_off = warp_n * 32 + j * 16;
            wmma::load_matrix_sync(bh[j], Bh + n_off * 40 + ks * 16, 40);
            wmma::load_matrix_sync(bl[j], Bl + n_off * 40 + ks * 16, 40);
        }
        #pragma unroll
        for (int i = 0; i < 4; i++) {
            int m_off = warp_m * 64 + i * 16;
            wmma::fragment<wmma::matrix_a, 16, 16, 16, __nv_bfloat16, wmma::row_major> ah, al;
            wmma::load_matrix_sync(ah, Ah + m_off * 40 + ks * 16, 40);
            wmma::load_matrix_sync(al, Al + m_off * 40 + ks * 16, 40);
            #pragma unroll
            for (int j = 0; j < 2; j++) {
                wmma::mma_sync(acc[i][j], ah, bh[j], acc[i][j]);
                wmma::mma_sync(acc[i][j], al, bh[j], acc[i][j]);
                wmma::mma_sync(acc[i][j], ah, bl[j], acc[i][j]);
            }
        }
    }
}

// B in smem as [k rows][n cols] row-major, ldm 136 (pv)
__device__ __forceinline__ void mma_chunk_rowB(
    const char* buf, int warp_m, int warp_n, AccFrag (&acc)[4][2])
{
    const __nv_bfloat16* Ah = (const __nv_bfloat16*)(buf);
    const __nv_bfloat16* Al = (const __nv_bfloat16*)(buf + OFF_AL);
    const __nv_bfloat16* Bh = (const __nv_bfloat16*)(buf + OFF_BH);
    const __nv_bfloat16* Bl = (const __nv_bfloat16*)(buf + OFF_BL);
    #pragma unroll
    for (int ks = 0; ks < 2; ks++) {
        wmma::fragment<wmma::matrix_b, 16, 16, 16, __nv_bfloat16, wmma::row_major> bh[2], bl[2];
        #pragma unroll
        for (int j = 0; j < 2; j++) {
            int n_off = warp_n * 32 + j * 16;
            wmma::load_matrix_sync(bh[j], Bh + (ks * 16) * 136 + n_off, 136);
            wmma::load_matrix_sync(bl[j], Bl + (ks * 16) * 136 + n_off, 136);
        }
        #pragma unroll
        for (int i = 0; i < 4; i++) {
            int m_off = warp_m * 64 + i * 16;
            wmma::fragment<wmma::matrix_a, 16, 16, 16, __nv_bfloat16, wmma::row_major> ah, al;
            wmma::load_matrix_sync(ah, Ah + m_off * 40 + ks * 16, 40);
            wmma::load_matrix_sync(al, Al + m_off * 40 + ks * 16, 40);
            #pragma unroll
            for (int j = 0; j < 2; j++) {
                wmma::mma_sync(acc[i][j], ah, bh[j], acc[i][j]);
                wmma::mma_sync(acc[i][j], al, bh[j], acc[i][j]);
                wmma::mma_sync(acc[i][j], ah, bl[j], acc[i][j]);
            }
        }
    }
}

#define EPILOGUE_STORE() \
    __syncthreads(); \
    { \
        float* Cs = (float*)smem; \
        wmma::store_matrix_sync(Cs + (warp_m * 64) * 128 + warp_n * 32, acc[0][0], 128, wmma::mem_row_major); \
        wmma::store_matrix_sync(Cs + (warp_m * 64) * 128 + warp_n * 32 + 16, acc[0][1], 128, wmma::mem_row_major); \
        wmma::store_matrix_sync(Cs + (warp_m * 64 + 16) * 128 + warp_n * 32, acc[1][0], 128, wmma::mem_row_major); \
        wmma::store_matrix_sync(Cs + (warp_m * 64 + 16) * 128 + warp_n * 32 + 16, acc[1][1], 128, wmma::mem_row_major); \
        wmma::store_matrix_sync(Cs + (warp_m * 64 + 32) * 128 + warp_n * 32, acc[2][0], 128, wmma::mem_row_major); \
        wmma::store_matrix_sync(Cs + (warp_m * 64 + 32) * 128 + warp_n * 32 + 16, acc[2][1], 128, wmma::mem_row_major); \
        wmma::store_matrix_sync(Cs + (warp_m * 64 + 48) * 128 + warp_n * 32, acc[3][0], 128, wmma::mem_row_major); \
        wmma::store_matrix_sync(Cs + (warp_m * 64 + 48) * 128 + warp_n * 32 + 16, acc[3][1], 128, wmma::mem_row_major); \
    } \
    __syncthreads();

#define DECL_ACC() \
    AccFrag acc[4][2]; \
    _Pragma("unroll") \
    for (int i = 0; i < 4; i++) \
        _Pragma("unroll") \
        for (int j = 0; j < 2; j++) wmma::fill_fragment(acc[i][j], 0.0f);

// ============================================================
// qkv_wm: 3 projections in one launch. grid (64, 2, 24), block 256.
// z = c + 8*proj.  out layout [n][c][g*8+w].
// ============================================================
__global__ void __launch_bounds__(256)
qkv_wm(const float* __restrict__ A0, const float* __restrict__ A1, const float* __restrict__ A2,
       const float* __restrict__ W0, const float* __restrict__ W1, const float* __restrict__ W2,
       float* __restrict__ O0, float* __restrict__ O1, float* __restrict__ O2) {
    extern __shared__ char smem[];
    const int tid = threadIdx.x;
    const int warp_m = (tid >> 5) >> 2, warp_n = (tid >> 5) & 3;
    const int c = blockIdx.z & 7, proj = blockIdx.z >> 3;
    const int m0 = blockIdx.x * 128, g0 = blockIdx.y * 128;
    const float* A = (proj == 0) ? A0 : (proj == 1) ? A1 : A2;
    const float* W = (proj == 0) ? W0 : (proj == 1) ? W1 : W2;
    float* out     = (proj == 0) ? O0 : (proj == 1) ? O1 : O2;

    DECL_ACC();
    float4 ra[4], rb[4];
    const int n_l = tid >> 6, p4 = tid & 63;       // A indexing (fixed per thread)
    const int g_l = tid >> 3, h4 = tid & 7;        // B indexing
    const float* Abase = A + (size_t)(m0 >> 3) * 16384 + c * 2048;
    const float* Wbase = W + (size_t)c * 65536 + (size_t)g0 * 256;

    #define QKV_LOAD(kc) { \
        const int h0 = (kc) * 32; \
        _Pragma("unroll") \
        for (int it = 0; it < 4; it++) { \
            ra[it] = *(const float4*)(Abase + (size_t)(n_l + it*4) * 16384 + h0*8 + p4 * 4); \
            rb[it] = *(const float4*)(Wbase + (size_t)(g_l + it*32) * 256 + h0 + h4 * 4); \
        } }
    #define QKV_STORE(p) { \
        char* buf = smem + (p) * BUF_STRIDE; \
        __nv_bfloat16* Ah = (__nv_bfloat16*)buf; \
        __nv_bfloat16* Al = (__nv_bfloat16*)(buf + OFF_AL); \
        __nv_bfloat16* Bh = (__nv_bfloat16*)(buf + OFF_BH); \
        __nv_bfloat16* Bl = (__nv_bfloat16*)(buf + OFF_BL); \
        _Pragma("unroll") \
        for (int it = 0; it < 4; it++) { \
            int p_ = p4 * 4, h_rel = p_ >> 3, w0 = p_ & 7; \
            int rbase = (n_l + it*4) * 8 + w0; \
            split_store(Ah, Al, (rbase + 0) * 40 + h_rel, ra[it].x); \
            split_store(Ah, Al, (rbase + 1) * 40 + h_rel, ra[it].y); \
            split_store(Ah, Al, (rbase + 2) * 40 + h_rel, ra[it].z); \
            split_store(Ah, Al, (rbase + 3) * 40 + h_rel, ra[it].w); \
            int cb = (g_l + it*32) * 40 + h4 * 4; \
            split_store(Bh, Bl, cb + 0, rb[it].x); \
            split_store(Bh, Bl, cb + 1, rb[it].y); \
            split_store(Bh, Bl, cb + 2, rb[it].z); \
            split_store(Bh, Bl, cb + 3, rb[it].w); \
        } }

    QKV_LOAD(0);
    for (int kc = 0; kc < 8; kc++) {
        QKV_STORE(kc & 1);
        __syncthreads();
        if (kc < 7) QKV_LOAD(kc + 1);
        mma_chunk_colB(smem + (kc & 1) * BUF_STRIDE, warp_m, warp_n, acc);
    }

    EPILOGUE_STORE();
    const float* Cs = (const float*)smem;
    const int col = tid & 127;
    for (int jj = 0; jj < 64; jj++) {
        int r = jj * 2 + (tid >> 7);
        int n = (m0 + r) >> 3, w = r & 7, g = g0 + col;
        out[(size_t)n * 16384 + c * 2048 + g * 8 + w] = Cs[r * 128 + col];
    }
}

// ============================================================
// olin_wm: final wo projection. grid (64, 2, 8), block 256.
// ============================================================
__global__ void __launch_bounds__(256)
olin_wm(const float* __restrict__ A, const float* __restrict__ W,
        float* __restrict__ out) {
    extern __shared__ char smem[];
    const int tid = threadIdx.x;
    const int warp_m = (tid >> 5) >> 2, warp_n = (tid >> 5) & 3;
    const int c = blockIdx.z, m0 = blockIdx.x * 128, g0 = blockIdx.y * 128;

    DECL_ACC();
    float4 ra[4], rb[4];
    const int n_l = tid >> 6, p4 = tid & 63;
    const int g_l = tid >> 3, h4 = tid & 7;
    const float* Abase = A + (size_t)(m0 >> 3) * 16384 + c * 2048;
    const float* Wbase = W + (size_t)c * 65536 + (size_t)g0 * 256;

    QKV_LOAD(0);
    for (int kc = 0; kc < 8; kc++) {
        QKV_STORE(kc & 1);
        __syncthreads();
        if (kc < 7) QKV_LOAD(kc + 1);
        mma_chunk_colB(smem + (kc & 1) * BUF_STRIDE, warp_m, warp_n, acc);
    }

    EPILOGUE_STORE();
    const float* Cs = (const float*)smem;
    const int col = tid & 127;
    for (int jj = 0; jj < 64; jj++) {
        int r = jj * 2 + (tid >> 7);
        int n = (m0 + r) >> 3, w = r & 7, g = g0 + col;
        int b = n >> 9, l = n & 511;
        out[((size_t)(b * 8 + c) * 512 + l) * 2048 + g * 8 + w] = Cs[r * 128 + col];
    }
}

// ============================================================
// qk_wm: grid (4, 4, 128), block 256.
// ============================================================
__global__ void __launch_bounds__(256)
qk_wm(const float* __restrict__ prev, float* __restrict__ qk) {
    extern __shared__ char smem[];
    const int tid = threadIdx.x;
    const int warp_m = (tid >> 5) >> 2, warp_n = (tid >> 5) & 3;
    const int z = blockIdx.z;
    const int b = z >> 6, c = (z >> 3) & 7, nh = z & 7;
    const int l0 = blockIdx.y * 128, m0 = blockIdx.x * 128;
    const float* qb = g_q + (size_t)b * 512 * 16384 + c * 2048 + nh * 256;
    const float* kb = g_k + (size_t)b * 512 * 16384 + c * 2048 + nh * 256;

    DECL_ACC();
    float4 ra[4], rb[4];
    const int r_l = tid >> 3, d4 = tid & 7;   // 32 rows per it-step? r = r_l + it*32

    #define QK_LOAD(kc) { \
        const int k0 = (kc) * 32; \
        _Pragma("unroll") \
        for (int it = 0; it < 4; it++) { \
            int r = r_l + it * 32; \
            ra[it] = *(const float4*)(qb + (size_t)(l0 + r) * 16384 + k0 + d4 * 4); \
            rb[it] = *(const float4*)(kb + (size_t)(m0 + r) * 16384 + k0 + d4 * 4); \
        } }
    #define QK_STORE(p) { \
        char* buf = smem + (p) * BUF_STRIDE; \
        __nv_bfloat16* Ah = (__nv_bfloat16*)buf; \
        __nv_bfloat16* Al = (__nv_bfloat16*)(buf + OFF_AL); \
        __nv_bfloat16* Bh = (__nv_bfloat16*)(buf + OFF_BH); \
        __nv_bfloat16* Bl = (__nv_bfloat16*)(buf + OFF_BL); \
        _Pragma("unroll") \
        for (int it = 0; it < 4; it++) { \
            int cb = (r_l + it * 32) * 40 + d4 * 4; \
            split_store(Ah, Al, cb + 0, ra[it].x); \
            split_store(Ah, Al, cb + 1, ra[it].y); \
            split_store(Ah, Al, cb + 2, ra[it].z); \
            split_store(Ah, Al, cb + 3, ra[it].w); \
            split_store(Bh, Bl, cb + 0, rb[it].x); \
            split_store(Bh, Bl, cb + 1, rb[it].y); \
            split_store(Bh, Bl, cb + 2, rb[it].z); \
            split_store(Bh, Bl, cb + 3, rb[it].w); \
        } }

    QK_LOAD(0);
    for (int kc = 0; kc < 8; kc++) {
        QK_STORE(kc & 1);
        __syncthreads();
        if (kc < 7) QK_LOAD(kc + 1);
        mma_chunk_colB(smem + (kc & 1) * BUF_STRIDE, warp_m, warp_n, acc);
    }

    EPILOGUE_STORE();
    const float* Cs = (const float*)smem;
    const int col = tid & 127;
    for (int jj = 0; jj < 64; jj++) {
        int r = jj * 2 + (tid >> 7);
        size_t idx = (size_t)z * LL + (size_t)(l0 + r) * 512 + m0 + col;
        qk[idx] = Cs[r * 128 + col] * 0.0625f + prev[idx];
    }
}

// ============================================================
// pv_wm: grid (2, 4, 128), block 256. K=512 -> 16 chunks.
// ============================================================
__global__ void __launch_bounds__(256)
pv_wm(const float* __restrict__ qkv) {
    extern __shared__ char smem[];
    float* rmx  = (float*)(smem + SM_RMX);
    float* rinv = (float*)(smem + SM_RINV);
    const int tid = threadIdx.x;
    const int warp_m = (tid >> 5) >> 2, warp_n = (tid >> 5) & 3;
    const int z = blockIdx.z;
    const int b = z >> 6, c = (z >> 3) & 7, nh = z & 7;
    const int l0 = blockIdx.y * 128, d0 = blockIdx.x * 128;
    const float* vb = g_v + (size_t)b * 512 * 16384 + c * 2048 + nh * 256;

    if (tid < 128) {
        rmx[tid]  = g_rmax[z * 512 + l0 + tid];
        rinv[tid] = 1.0f / g_rsum[z * 512 + l0 + tid];
    }
    __syncthreads();

    DECL_ACC();
    float4 ra[4], rb[4];
    const int r_l = tid >> 3, d4 = tid & 7;      // A: rows l
    const int m_l = tid >> 5, dv4 = tid & 31;    // B: rows m (k), cols d

    #define PV_LOAD(kc) { \
        const int k0 = (kc) * 32; \
        _Pragma("unroll") \
        for (int it = 0; it < 4; it++) { \
            int r = r_l + it * 32; \
            ra[it] = *(const float4*)(qkv + (size_t)z * LL + (size_t)(l0 + r) * 512 + k0 + d4 * 4); \
            rb[it] = *(const float4*)(vb + (size_t)(k0 + m_l + it * 8) * 16384 + d0 + dv4 * 4); \
        } }
    #define PV_STORE(p) { \
        char* buf = smem + (p) * BUF_STRIDE; \
        __nv_bfloat16* Ah = (__nv_bfloat16*)buf; \
        __nv_bfloat16* Al = (__nv_bfloat16*)(buf + OFF_AL); \
        __nv_bfloat16* Bh = (__nv_bfloat16*)(buf + OFF_BH); \
        __nv_bfloat16* Bl = (__nv_bfloat16*)(buf + OFF_BL); \
        _Pragma("unroll") \
        for (int it = 0; it < 4; it++) { \
            int r = r_l + it * 32; \
            float mx = rmx[r]; \
            float ex0 = __expf(ra[it].x - mx), ex1 = __expf(ra[it].y - mx); \
            float ex2 = __expf(ra[it].z - mx), ex3 = __expf(ra[it].w - mx); \
            int cb = r * 40 + d4 * 4; \
            split_store(Ah, Al, cb + 0, ex0); \
            split_store(Ah, Al, cb + 1, ex1); \
            split_store(Ah, Al, cb + 2, ex2); \
            split_store(Ah, Al, cb + 3, ex3); \
            int vbi = (m_l + it * 8) * 136 + dv4 * 4; \
            split_store(Bh, Bl, vbi + 0, rb[it].x); \
            split_store(Bh, Bl, vbi + 1, rb[it].y); \
            split_store(Bh, Bl, vbi + 2, rb[it].z); \
            split_store(Bh, Bl, vbi + 3, rb[it].w); \
        } }

    PV_LOAD(0);
    for (int kc = 0; kc < 16; kc++) {
        PV_STORE(kc & 1);
        __syncthreads();
        if (kc < 15) PV_LOAD(kc + 1);
        mma_chunk_rowB(smem + (kc & 1) * BUF_STRIDE, warp_m, warp_n, acc);
    }

    EPILOGUE_STORE();
    const float* Cs = (const float*)smem;
    const int col = tid & 127;
    for (int jj = 0; jj < 64; jj++) {
        int r = jj * 2 + (tid >> 7);
        int l = l0 + r;
        float v = Cs[r * 128 + col] * rinv[r];
        int f = nh * 256 + d0 + col;
        g_a[(size_t)(b * 512 + l) * 16384 + c * 2048 + f] = v;
    }
}

// ============================================================
// conv3 / rope / stats (validated)
// ============================================================
__global__ void conv3_kernel(const float* __restrict__ x,
                             const float* __restrict__ wq,
                             const float* __restrict__ wk,
                             const float* __restrict__ wv) {
    __shared__ float xt[8*66*10];
    __shared__ float wsm[3*576];
    const int n  = blockIdx.x;
    const int y0 = blockIdx.y * 64;
    const int b  = n >> 9, l = n & 511;
    const int tid = threadIdx.x;

    for (int i = tid; i < 576; i += 256) {
        wsm[i] = wq[i]; wsm[576 + i] = wk[i]; wsm[1152 + i] = wv[i];
    }
    for (int i = tid; i < 8*66*10; i += 256) {
        int ci = i / 660, rem = i % 660;
        int yy = rem / 10, xx = rem % 10;
        int y = y0 + yy - 1, xc = xx - 1;
        float v = 0.f;
        if (y >= 0 && y < 256 && xc >= 0 && xc < 8)
            v = x[(((size_t)(b*C + ci)*L + l)*256 + y)*8 + xc];
        xt[i] = v;
    }
    __syncthreads();

    const int yb = tid >> 3, w = tid & 7;
    float acc[2][24];
    #pragma unroll
    for (int r = 0; r < 2; r++)
        #pragma unroll
        for (int o = 0; o < 24; o++) acc[r][o] = 0.f;

    for (int ci = 0; ci < 8; ci++) {
        float xv[2][9];
        #pragma unroll
        for (int r = 0; r < 2; r++)
            #pragma unroll
            for (int ky = 0; ky < 3; ky++)
                #pragma unroll
                for (int kx = 0; kx < 3; kx++)
                    xv[r][ky*3 + kx] = xt[ci*660 + (yb + r*32 + ky)*10 + (w + kx)];
        #pragma unroll
        for (int o = 0; o < 24; o++) {
            int p = o >> 3, co = o & 7;
            const float* wp = &wsm[p*576 + (co*8 + ci)*9];
            #pragma unroll
            for (int k9 = 0; k9 < 9; k9++) {
                float ww = wp[k9];
                acc[0][o] += xv[0][k9] * ww;
                acc[1][o] += xv[1][k9] * ww;
            }
        }
    }
    #pragma unroll
    for (int p = 0; p < 3; p++) {
        float* op = (p == 0) ? g_conv0 : (p == 1) ? g_conv1 : g_conv2;
        #pragma unroll
        for (int co = 0; co < 8; co++)
            #pragma unroll
            for (int r = 0; r < 2; r++)
                op[(size_t)n*16384 + co*2048 + (size_t)(y0 + yb + r*32)*8 + w] = acc[r][p*8 + co];
    }
}

__global__ void rope_kernel() {
    int t = blockIdx.x * 256 + threadIdx.x;
    int j  = t & 15;  t >>= 4;
    int nh = t & 7;   t >>= 3;
    int c  = t & 7;   t >>= 3;
    int l  = t & 511; t >>= 9;
    int b  = t;
    size_t base = (size_t)(b*L + l)*16384 + c*2048 + nh*256 + 2*j;
    float invf = powf(10000.f, -(float)j / 16.f);
    float sn, cs;
    sincosf((float)l * invf, &sn, &cs);
    float q0 = g_q[base], q1 = g_q[base + 1];
    g_q[base]     = q0*cs - q1*sn;
    g_q[base + 1] = q1*cs + q0*sn;
    float k0 = g_k[base], k1 = g_k[base + 1];
    g_k[base]     = k0*cs - k1*sn;
    g_k[base + 1] = k1*cs + k0*sn;
}

__global__ void stats_kernel(const float* __restrict__ qk) {
    const int row = blockIdx.x;
    const int tid = threadIdx.x;
    const float4 v = reinterpret_cast<const float4*>(qk + (size_t)row*512)[tid];
    float mx = fmaxf(fmaxf(v.x, v.y), fmaxf(v.z, v.w));
    #pragma unroll
    for (int o = 16; o; o >>= 1) mx = fmaxf(mx, __shfl_xor_sync(~0u, mx, o));
    __shared__ float sm[4], ss[4];
    if ((tid & 31) == 0) sm[tid >> 5] = mx;
    __syncthreads();
    mx = fmaxf(fmaxf(sm[0], sm[1]), fmaxf(sm[2], sm[3]));
    float s = expf(v.x - mx) + expf(v.y - mx) + expf(v.z - mx) + expf(v.w - mx);
    #pragma unroll
    for (int o = 16; o; o >>= 1) s += __shfl_xor_sync(~0u, s, o);
    if ((tid & 31) == 0) ss[tid >> 5] = s;
    __syncthreads();
    if (tid == 0) {
        g_rmax[row] = mx;
        g_rsum[row] = ss[0] + ss[1] + ss[2] + ss[3];
    }
}

// ============================================================
extern "C" void kernel_launch(void* const* d_in, const int* in_sizes, int n_in,
                              void* d_out, int out_size) {
    const float* x    = (const float*)d_in[0];
    const float* prev = (const float*)d_in[1];
    const float* cw_q = (const float*)d_in[2];
    const float* cw_k = (const float*)d_in[3];
    const float* cw_v = (const float*)d_in[4];
    const float* wq   = (const float*)d_in[5];
    const float* wk   = (const float*)d_in[6];
    const float* wv   = (const float*)d_in[7];
    const float* wo   = (const float*)d_in[8];
    float* out    = (float*)d_out;
    float* qk_out = out + (size_t)NCF;

    float *p_c0, *p_c1, *p_c2, *p_q, *p_k, *p_v, *p_a;
    cudaGetSymbolAddress((void**)&p_c0, g_conv0);
    cudaGetSymbolAddress((void**)&p_c1, g_conv1);
    cudaGetSymbolAddress((void**)&p_c2, g_conv2);
    cudaGetSymbolAddress((void**)&p_q,  g_q);
    cudaGetSymbolAddress((void**)&p_k,  g_k);
    cudaGetSymbolAddress((void**)&p_v,  g_v);
    cudaGetSymbolAddress((void**)&p_a,  g_a);

    cudaFuncSetAttribute(qkv_wm, cudaFuncAttributeMaxDynamicSharedMemorySize, SMEM_BYTES);
    cudaFuncSetAttribute(olin_wm, cudaFuncAttributeMaxDynamicSharedMemorySize, SMEM_BYTES);
    cudaFuncSetAttribute(qk_wm,   cudaFuncAttributeMaxDynamicSharedMemorySize, SMEM_BYTES);
    cudaFuncSetAttribute(pv_wm,   cudaFuncAttributeMaxDynamicSharedMemorySize, SMEM_BYTES);

    conv3_kernel<<<dim3(1024, 4), 256>>>(x, cw_q, cw_k, cw_v);
    qkv_wm<<<dim3(64, 2, 24), 256, SMEM_BYTES>>>(p_c0, p_c1, p_c2, wq, wk, wv, p_q, p_k, p_v);
    rope_kernel<<<4096, 256>>>();
    qk_wm<<<dim3(4, 4, 128), 256, SMEM_BYTES>>>(prev, qk_out);
    stats_kernel<<<65536, 128>>>(qk_out);
    pv_wm<<<dim3(2, 4, 128), 256, SMEM_BYTES>>>(qk_out);
    olin_wm<<<dim3(64, 2, 8), 256, SMEM_BYTES>>>(p_a, wo, out);
}

// round 6
// speedup vs baseline: 2.1295x; 1.1889x over previous
#include <cuda_runtime.h>
#include <cuda_bf16.h>
#include <mma.h>
#include <math.h>
#include <cstdint>

using namespace nvcuda;
typedef __nv_bfloat16 bf16;

#define C    8
#define L    512
#define NCF  (1024*8*2048)     // 16,777,216
#define LL   (512*512)

// ---- bf16 hi/lo scratch ----
__device__ bf16 g_c0h[NCF], g_c0l[NCF];
__device__ bf16 g_c1h[NCF], g_c1l[NCF];
__device__ bf16 g_c2h[NCF], g_c2l[NCF];
__device__ bf16 g_qh[NCF],  g_ql[NCF];
__device__ bf16 g_kh[NCF],  g_kl[NCF];
__device__ bf16 g_vh[NCF],  g_vl[NCF];
__device__ bf16 g_ah[NCF],  g_al[NCF];
__device__ bf16 g_wh[4*C*65536], g_wl[4*C*65536];
__device__ float g_rmax[65536], g_rsum[65536];

// ---- helpers ----
__device__ __forceinline__ uint32_t s2u(const void* p) {
    return (uint32_t)__cvta_generic_to_shared(p);
}
__device__ __forceinline__ void cpa16(uint32_t s, const void* g) {
    asm volatile("cp.async.cg.shared.global [%0], [%1], 16;" :: "r"(s), "l"(g));
}
#define CPCOMMIT() asm volatile("cp.async.commit_group;" ::: "memory")
#define CPWAIT()   asm volatile("cp.async.wait_group 0;" ::: "memory")

__device__ __forceinline__ void bsplit(float x, bf16& h, bf16& l) {
    h = __float2bfloat16(x);
    l = __float2bfloat16(x - __bfloat162float(h));
}
__device__ __forceinline__ uint32_t packbf2(bf16 a, bf16 b) {
    __nv_bfloat162 t; t.x = a; t.y = b;
    return *(uint32_t*)&t;
}
__device__ __forceinline__ void pack8(const float* v, uint4& H, uint4& Lo) {
    bf16 h[8], l[8];
    #pragma unroll
    for (int i = 0; i < 8; i++) bsplit(v[i], h[i], l[i]);
    H  = make_uint4(packbf2(h[0],h[1]), packbf2(h[2],h[3]), packbf2(h[4],h[5]), packbf2(h[6],h[7]));
    Lo = make_uint4(packbf2(l[0],l[1]), packbf2(l[2],l[3]), packbf2(l[4],l[5]), packbf2(l[6],l[7]));
}

typedef wmma::fragment<wmma::accumulator, 16, 16, 16, float> AccFrag;

// stage layouts (bytes), per 37888/40960-byte buffer:
//  qk  : Qh 0 (10240) Ql 10240 Kh 20480 Kl 30720   [all K-major 128x40, ldm 40]
//  qkv : Wh 0 (10240) Wl 10240 ATh 20480 (8704) ATl 29184  [AT: 32x136, ldm 136]
//  pv  : Ph 0 (10240) Pl 10240 Vh 20480 (8704) Vl 29184    [V: k x d, ldm 136]

// A row_major K-major (ldm 40); B col_major K-major (ldm 40)  [proven: qk]
__device__ __forceinline__ void mma_rAcB(const char* buf, int wm, int wn, AccFrag (&acc)[4][2]) {
    const bf16* Ah = (const bf16*)(buf);
    const bf16* Al = (const bf16*)(buf + 10240);
    const bf16* Bh = (const bf16*)(buf + 20480);
    const bf16* Bl = (const bf16*)(buf + 30720);
    #pragma unroll
    for (int ks = 0; ks < 2; ks++) {
        wmma::fragment<wmma::matrix_b, 16, 16, 16, bf16, wmma::col_major> bh[2], bl[2];
        #pragma unroll
        for (int j = 0; j < 2; j++) {
            int n_off = wn * 32 + j * 16;
            wmma::load_matrix_sync(bh[j], Bh + n_off * 40 + ks * 16, 40);
            wmma::load_matrix_sync(bl[j], Bl + n_off * 40 + ks * 16, 40);
        }
        #pragma unroll
        for (int i = 0; i < 4; i++) {
            int m_off = wm * 64 + i * 16;
            wmma::fragment<wmma::matrix_a, 16, 16, 16, bf16, wmma::row_major> ah, al;
            wmma::load_matrix_sync(ah, Ah + m_off * 40 + ks * 16, 40);
            wmma::load_matrix_sync(al, Al + m_off * 40 + ks * 16, 40);
            #pragma unroll
            for (int j = 0; j < 2; j++) {
                wmma::mma_sync(acc[i][j], ah, bh[j], acc[i][j]);
                wmma::mma_sync(acc[i][j], al, bh[j], acc[i][j]);
                wmma::mma_sync(acc[i][j], ah, bl[j], acc[i][j]);
            }
        }
    }
}

// A row_major K-major (ldm 40); B row_major [k][n] (ldm 136)  [proven: pv]
__device__ __forceinline__ void mma_rArB(const char* buf, int wm, int wn, AccFrag (&acc)[4][2]) {
    const bf16* Ah = (const bf16*)(buf);
    const bf16* Al = (const bf16*)(buf + 10240);
    const bf16* Bh = (const bf16*)(buf + 20480);
    const bf16* Bl = (const bf16*)(buf + 29184);
    #pragma unroll
    for (int ks = 0; ks < 2; ks++) {
        wmma::fragment<wmma::matrix_b, 16, 16, 16, bf16, wmma::row_major> bh[2], bl[2];
        #pragma unroll
        for (int j = 0; j < 2; j++) {
            int n_off = wn * 32 + j * 16;
            wmma::load_matrix_sync(bh[j], Bh + (ks * 16) * 136 + n_off, 136);
            wmma::load_matrix_sync(bl[j], Bl + (ks * 16) * 136 + n_off, 136);
        }
        #pragma unroll
        for (int i = 0; i < 4; i++) {
            int m_off = wm * 64 + i * 16;
            wmma::fragment<wmma::matrix_a, 16, 16, 16, bf16, wmma::row_major> ah, al;
            wmma::load_matrix_sync(ah, Ah + m_off * 40 + ks * 16, 40);
            wmma::load_matrix_sync(al, Al + m_off * 40 + ks * 16, 40);
            #pragma unroll
            for (int j = 0; j < 2; j++) {
                wmma::mma_sync(acc[i][j], ah, bh[j], acc[i][j]);
                wmma::mma_sync(acc[i][j], al, bh[j], acc[i][j]);
                wmma::mma_sync(acc[i][j], ah, bl[j], acc[i][j]);
            }
        }
    }
}

#define DECL_ACC() \
    AccFrag acc[4][2]; \
    _Pragma("unroll") for (int i_ = 0; i_ < 4; i_++) \
        _Pragma("unroll") for (int j_ = 0; j_ < 2; j_++) wmma::fill_fragment(acc[i_][j_], 0.0f);

#define EPI_TO_CS() \
    __syncthreads(); \
    { float* Cs_ = (float*)smem; \
      _Pragma("unroll") for (int i_ = 0; i_ < 4; i_++) \
        _Pragma("unroll") for (int j_ = 0; j_ < 2; j_++) \
          wmma::store_matrix_sync(Cs_ + (wm*64 + i_*16)*132 + wn*32 + j_*16, acc[i_][j_], 132, wmma::mem_row_major); } \
    __syncthreads();

// ============================================================
// prep_w: split 4 weight tensors to bf16 hi/lo.  grid 8192 x 256.
// ============================================================
__global__ void prep_w(const float* __restrict__ wq, const float* __restrict__ wk,
                       const float* __restrict__ wv, const float* __restrict__ wo) {
    int idx = blockIdx.x * 256 + threadIdx.x;
    int t = idx >> 19, off = idx & 524287;
    const float* src = (t == 0) ? wq : (t == 1) ? wk : (t == 2) ? wv : wo;
    bf16 h, l;
    bsplit(src[off], h, l);
    g_wh[idx] = h; g_wl[idx] = l;
}

// ============================================================
// conv3: fused 3x conv3x3 -> bf16 hi/lo outputs [n][c][h*8+w]
// ============================================================
__global__ void conv3_kernel(const float* __restrict__ x,
                             const float* __restrict__ wq,
                             const float* __restrict__ wk,
                             const float* __restrict__ wv) {
    __shared__ float xt[8*66*10];
    __shared__ float wsm[3*576];
    const int n  = blockIdx.x;
    const int y0 = blockIdx.y * 64;
    const int b  = n >> 9, l = n & 511;
    const int tid = threadIdx.x;

    for (int i = tid; i < 576; i += 256) {
        wsm[i] = wq[i]; wsm[576 + i] = wk[i]; wsm[1152 + i] = wv[i];
    }
    for (int i = tid; i < 8*66*10; i += 256) {
        int ci = i / 660, rem = i % 660;
        int yy = rem / 10, xx = rem % 10;
        int y = y0 + yy - 1, xc = xx - 1;
        float v = 0.f;
        if (y >= 0 && y < 256 && xc >= 0 && xc < 8)
            v = x[(((size_t)(b*C + ci)*L + l)*256 + y)*8 + xc];
        xt[i] = v;
    }
    __syncthreads();

    const int yb = tid >> 3, w = tid & 7;
    float acc[2][24];
    #pragma unroll
    for (int r = 0; r < 2; r++)
        #pragma unroll
        for (int o = 0; o < 24; o++) acc[r][o] = 0.f;

    for (int ci = 0; ci < 8; ci++) {
        float xv[2][9];
        #pragma unroll
        for (int r = 0; r < 2; r++)
            #pragma unroll
            for (int ky = 0; ky < 3; ky++)
                #pragma unroll
                for (int kx = 0; kx < 3; kx++)
                    xv[r][ky*3 + kx] = xt[ci*660 + (yb + r*32 + ky)*10 + (w + kx)];
        #pragma unroll
        for (int o = 0; o < 24; o++) {
            int p = o >> 3, co = o & 7;
            const float* wp = &wsm[p*576 + (co*8 + ci)*9];
            #pragma unroll
            for (int k9 = 0; k9 < 9; k9++) {
                float ww = wp[k9];
                acc[0][o] += xv[0][k9] * ww;
                acc[1][o] += xv[1][k9] * ww;
            }
        }
    }
    #pragma unroll
    for (int p = 0; p < 3; p++) {
        bf16* oh = (p == 0) ? g_c0h : (p == 1) ? g_c1h : g_c2h;
        bf16* ol = (p == 0) ? g_c0l : (p == 1) ? g_c1l : g_c2l;
        #pragma unroll
        for (int co = 0; co < 8; co++)
            #pragma unroll
            for (int r = 0; r < 2; r++) {
                size_t off = (size_t)n*16384 + co*2048 + (size_t)(y0 + yb + r*32)*8 + w;
                bf16 hh, lv;
                bsplit(acc[r][p*8 + co], hh, lv);
                oh[off] = hh; ol[off] = lv;
            }
    }
}

// ============================================================
// qkv_wm: 3 projections, computed TRANSPOSED: outT[g][m] = W[g][:].AT[:][m]
// A-frag = W K-major rows (row_major, ldm 40); B-frag = AT [k][m] (row_major, ldm 136)
// grid (64, 2, 24), block 256, 2 CTAs/SM.  Out -> hi/lo bf16 [n][c][g*8+w].
// ============================================================
#define QKV_SMEM 75776
__global__ void __launch_bounds__(256, 2)
qkv_wm() {
    extern __shared__ __align__(16) char smem[];
    const uint32_t sb = s2u(smem);
    const int tid = threadIdx.x, wid = tid >> 5;
    const int wm = wid >> 2, wn = wid & 3;
    const int c = blockIdx.z & 7, proj = blockIdx.z >> 3;
    const int m0 = blockIdx.x * 128, g0 = blockIdx.y * 128, n0 = m0 >> 3;
    const bf16* Ah_g = (proj == 0) ? g_c0h : (proj == 1) ? g_c1h : g_c2h;
    const bf16* Al_g = (proj == 0) ? g_c0l : (proj == 1) ? g_c1l : g_c2l;
    const bf16* Wh_g = g_wh + (size_t)proj * 524288;
    const bf16* Wl_g = g_wl + (size_t)proj * 524288;
    bf16* Oh = (proj == 0) ? g_qh : (proj == 1) ? g_kh : g_vh;
    bf16* Ol = (proj == 0) ? g_ql : (proj == 1) ? g_kl : g_vl;

    DECL_ACC();

    #define QKVLD(s, kc) { \
        uint32_t sbase = sb + (s) * 37888; int k0 = (kc) * 32; \
        _Pragma("unroll") for (int i = 0; i < 2; i++) { \
            int ch = tid + i * 256; \
            int gr = ch >> 2, c4 = ch & 3; \
            size_t gb = (size_t)c * 65536 + (size_t)(g0 + gr) * 256 + k0 + c4 * 8; \
            cpa16(sbase + gr * 80 + c4 * 16,         Wh_g + gb); \
            cpa16(sbase + 10240 + gr * 80 + c4 * 16, Wl_g + gb); \
            int hr = ch >> 4, nl = ch & 15; \
            size_t ga = (size_t)(n0 + nl) * 16384 + c * 2048 + (size_t)(k0 + hr) * 8; \
            cpa16(sbase + 20480 + hr * 272 + nl * 16, Ah_g + ga); \
            cpa16(sbase + 29184 + hr * 272 + nl * 16, Al_g + ga); \
        } }

    QKVLD(0, 0); CPCOMMIT();
    for (int kc = 0; kc < 8; kc++) {
        CPWAIT(); __syncthreads();
        if (kc < 7) { QKVLD((kc + 1) & 1, kc + 1); CPCOMMIT(); }
        mma_rArB(smem + (kc & 1) * 37888, wm, wn, acc);
    }

    // Cs holds outT: row = g_rel, col = m_rel = (n-n0)*8 + w
    EPI_TO_CS();
    const float* Cs = (const float*)smem;
    #pragma unroll
    for (int it = 0; it < 8; it++) {
        int p = tid + it * 256;
        int gr = p >> 4, nl = p & 15;
        const float* src = Cs + gr * 132 + nl * 8;
        float v[8];
        #pragma unroll
        for (int w = 0; w < 8; w++) v[w] = src[w];
        uint4 H, Lo;
        pack8(v, H, Lo);
        size_t e = (size_t)(n0 + nl) * 16384 + (size_t)c * 2048 + (size_t)(g0 + gr) * 8;
        *(uint4*)(Oh + e) = H;
        *(uint4*)(Ol + e) = Lo;
    }
}

// ============================================================
// rope on hi/lo bf16 q/k (first 32 dims). grid 4096 x 256.
// ============================================================
__global__ void rope_kernel() {
    int t = blockIdx.x * 256 + threadIdx.x;
    int j  = t & 15;  t >>= 4;
    int nh = t & 7;   t >>= 3;
    int c  = t & 7;   t >>= 3;
    int l  = t & 511; t >>= 9;
    int b  = t;
    size_t base = (size_t)(b*512 + l)*16384 + c*2048 + nh*256 + 2*j;
    float invf = powf(10000.f, -(float)j / 16.f);
    float sn, cs;
    sincosf((float)l * invf, &sn, &cs);
    float q0 = __bfloat162float(g_qh[base])   + __bfloat162float(g_ql[base]);
    float q1 = __bfloat162float(g_qh[base+1]) + __bfloat162float(g_ql[base+1]);
    float r0 = q0*cs - q1*sn, r1 = q1*cs + q0*sn;
    bf16 h, lo;
    bsplit(r0, h, lo); g_qh[base]   = h; g_ql[base]   = lo;
    bsplit(r1, h, lo); g_qh[base+1] = h; g_ql[base+1] = lo;
    float k0 = __bfloat162float(g_kh[base])   + __bfloat162float(g_kl[base]);
    float k1 = __bfloat162float(g_kh[base+1]) + __bfloat162float(g_kl[base+1]);
    r0 = k0*cs - k1*sn; r1 = k1*cs + k0*sn;
    bsplit(r0, h, lo); g_kh[base]   = h; g_kl[base]   = lo;
    bsplit(r1, h, lo); g_kh[base+1] = h; g_kl[base+1] = lo;
}

// ============================================================
// qk_wm: grid (4, 4, 128), block 256, 2 CTAs/SM.
// ============================================================
#define QK_SMEM 81920
__global__ void __launch_bounds__(256, 2)
qk_wm(const float* __restrict__ prev, float* __restrict__ qk) {
    extern __shared__ __align__(16) char smem[];
    const uint32_t sb = s2u(smem);
    const int tid = threadIdx.x, wid = tid >> 5;
    const int wm = wid >> 2, wn = wid & 3;
    const int z = blockIdx.z;
    const int b = z >> 6, c = (z >> 3) & 7, nh = z & 7;
    const int l0 = blockIdx.y * 128, m0 = blockIdx.x * 128;
    const size_t coff = (size_t)c * 2048 + nh * 256;
    const size_t bL = (size_t)b * 512;

    DECL_ACC();

    #define QKLD(s, kc) { \
        uint32_t sbase = sb + (s) * 40960; int k0 = (kc) * 32; \
        _Pragma("unroll") for (int i = 0; i < 2; i++) { \
            int ch = tid + i * 256; \
            int r = ch >> 2, c4 = ch & 3; \
            uint32_t so = r * 80 + c4 * 16; \
            size_t ga = (bL + l0 + r) * 16384 + coff + k0 + c4 * 8; \
            size_t gb = (bL + m0 + r) * 16384 + coff + k0 + c4 * 8; \
            cpa16(sbase + so,         g_qh + ga); \
            cpa16(sbase + 10240 + so, g_ql + ga); \
            cpa16(sbase + 20480 + so, g_kh + gb); \
            cpa16(sbase + 30720 + so, g_kl + gb); \
        } }

    QKLD(0, 0); CPCOMMIT();
    for (int kc = 0; kc < 8; kc++) {
        CPWAIT(); __syncthreads();
        if (kc < 7) { QKLD((kc + 1) & 1, kc + 1); CPCOMMIT(); }
        mma_rAcB(smem + (kc & 1) * 40960, wm, wn, acc);
    }

    EPI_TO_CS();
    const float* Cs = (const float*)smem;
    const int col = tid & 127;
    #pragma unroll 4
    for (int jj = 0; jj < 64; jj++) {
        int r = jj * 2 + (tid >> 7);
        size_t idx = (size_t)z * LL + (size_t)(l0 + r) * 512 + m0 + col;
        qk[idx] = Cs[r * 132 + col] * 0.0625f + prev[idx];
    }
}

// ============================================================
// stats: per-row max + sumexp. grid 65536 x 128.
// ============================================================
__global__ void stats_kernel(const float* __restrict__ qk) {
    const int row = blockIdx.x;
    const int tid = threadIdx.x;
    const float4 v = reinterpret_cast<const float4*>(qk + (size_t)row*512)[tid];
    float mx = fmaxf(fmaxf(v.x, v.y), fmaxf(v.z, v.w));
    #pragma unroll
    for (int o = 16; o; o >>= 1) mx = fmaxf(mx, __shfl_xor_sync(~0u, mx, o));
    __shared__ float sm[4], ss[4];
    if ((tid & 31) == 0) sm[tid >> 5] = mx;
    __syncthreads();
    mx = fmaxf(fmaxf(sm[0], sm[1]), fmaxf(sm[2], sm[3]));
    float s = expf(v.x - mx) + expf(v.y - mx) + expf(v.z - mx) + expf(v.w - mx);
    #pragma unroll
    for (int o = 16; o; o >>= 1) s += __shfl_xor_sync(~0u, s, o);
    if ((tid & 31) == 0) ss[tid >> 5] = s;
    __syncthreads();
    if (tid == 0) {
        g_rmax[row] = mx;
        g_rsum[row] = ss[0] + ss[1] + ss[2] + ss[3];
    }
}

// ============================================================
// pv_wm: grid (2, 4, 128), block 256, 2 CTAs/SM. K=512, 16 chunks.
// ============================================================
#define PV_SMEM 76800
__global__ void __launch_bounds__(256, 2)
pv_wm(const float* __restrict__ qkv) {
    extern __shared__ __align__(16) char smem[];
    const uint32_t sb = s2u(smem);
    const int tid = threadIdx.x, wid = tid >> 5;
    const int wm = wid >> 2, wn = wid & 3;
    const int z = blockIdx.z;
    const int b = z >> 6, c = (z >> 3) & 7, nh = z & 7;
    const int l0 = blockIdx.y * 128, d0 = blockIdx.x * 128;
    const size_t coff = (size_t)c * 2048 + nh * 256;
    const size_t bL = (size_t)b * 512;
    float* rinv = (float*)(smem + 75776);
    float* rmx  = (float*)(smem + 76288);
    if (tid < 128) {
        rmx[tid]  = g_rmax[z * 512 + l0 + tid];
        rinv[tid] = 1.0f / g_rsum[z * 512 + l0 + tid];
    }
    __syncthreads();

    DECL_ACC();
    float4 ra[4];
    const int rl = tid >> 3, d4 = tid & 7;

    #define PVARLD(kc) { int k0 = (kc) * 32; \
        _Pragma("unroll") for (int it = 0; it < 4; it++) \
            ra[it] = *(const float4*)(qkv + (size_t)z * LL + (size_t)(l0 + rl + it * 32) * 512 + k0 + d4 * 4); }

    #define PVASTS(s) { char* buf = smem + (s) * 37888; \
        _Pragma("unroll") for (int it = 0; it < 4; it++) { \
            int r = rl + it * 32; \
            float mx = rmx[r]; \
            float e0 = __expf(ra[it].x - mx), e1 = __expf(ra[it].y - mx); \
            float e2 = __expf(ra[it].z - mx), e3 = __expf(ra[it].w - mx); \
            bf16 h0, lo0, h1, lo1, h2, lo2, h3, lo3; \
            bsplit(e0, h0, lo0); bsplit(e1, h1, lo1); \
            bsplit(e2, h2, lo2); bsplit(e3, h3, lo3); \
            *(uint2*)(buf + r * 80 + d4 * 8)         = make_uint2(packbf2(h0, h1), packbf2(h2, h3)); \
            *(uint2*)(buf + 10240 + r * 80 + d4 * 8) = make_uint2(packbf2(lo0, lo1), packbf2(lo2, lo3)); \
        } }

    #define PVBLD(s, kc) { uint32_t sbase = sb + (s) * 37888; int k0 = (kc) * 32; \
        _Pragma("unroll") for (int i = 0; i < 2; i++) { \
            int ch = tid + i * 256; \
            int mr = ch >> 4, d8 = ch & 15; \
            size_t g = (bL + k0 + mr) * 16384 + coff + d0 + d8 * 8; \
            cpa16(sbase + 20480 + mr * 272 + d8 * 16, g_vh + g); \
            cpa16(sbase + 29184 + mr * 272 + d8 * 16, g_vl + g); \
        } }

    PVARLD(0);
    PVBLD(0, 0); CPCOMMIT();
    for (int kc = 0; kc < 16; kc++) {
        CPWAIT(); __syncthreads();
        PVASTS(kc & 1);
        if (kc < 15) { PVARLD(kc + 1); PVBLD((kc + 1) & 1, kc + 1); CPCOMMIT(); }
        __syncthreads();
        mma_rArB(smem + (kc & 1) * 37888, wm, wn, acc);
    }

    EPI_TO_CS();
    const float* Cs = (const float*)smem;
    #pragma unroll
    for (int it = 0; it < 8; it++) {
        int r = (tid >> 4) + it * 16;
        int col8 = (tid & 15) * 8;
        float4 a1 = *(const float4*)(Cs + r * 132 + col8);
        float4 a2 = *(const float4*)(Cs + r * 132 + col8 + 4);
        float iv = rinv[r];
        float v[8] = {a1.x*iv, a1.y*iv, a1.z*iv, a1.w*iv, a2.x*iv, a2.y*iv, a2.z*iv, a2.w*iv};
        uint4 H, Lo;
        pack8(v, H, Lo);
        size_t e = (bL + l0 + r) * 16384 + coff + d0 + col8;
        *(uint4*)(g_ah + e) = H;
        *(uint4*)(g_al + e) = Lo;
    }
}

// ============================================================
// olin_wm: wo projection, transposed formulation like qkv_wm. -> f32 out.
// ============================================================
__global__ void __launch_bounds__(256, 2)
olin_wm(float* __restrict__ out) {
    extern __shared__ __align__(16) char smem[];
    const uint32_t sb = s2u(smem);
    const int tid = threadIdx.x, wid = tid >> 5;
    const int wm = wid >> 2, wn = wid & 3;
    const int c = blockIdx.z, m0 = blockIdx.x * 128, g0 = blockIdx.y * 128, n0 = m0 >> 3;
    const bf16* Wh_g = g_wh + (size_t)3 * 524288;
    const bf16* Wl_g = g_wl + (size_t)3 * 524288;

    DECL_ACC();

    #define OLD(s, kc) { \
        uint32_t sbase = sb + (s) * 37888; int k0 = (kc) * 32; \
        _Pragma("unroll") for (int i = 0; i < 2; i++) { \
            int ch = tid + i * 256; \
            int gr = ch >> 2, c4 = ch & 3; \
            size_t gb = (size_t)c * 65536 + (size_t)(g0 + gr) * 256 + k0 + c4 * 8; \
            cpa16(sbase + gr * 80 + c4 * 16,         Wh_g + gb); \
            cpa16(sbase + 10240 + gr * 80 + c4 * 16, Wl_g + gb); \
            int hr = ch >> 4, nl = ch & 15; \
            size_t ga = (size_t)(n0 + nl) * 16384 + c * 2048 + (size_t)(k0 + hr) * 8; \
            cpa16(sbase + 20480 + hr * 272 + nl * 16, g_ah + ga); \
            cpa16(sbase + 29184 + hr * 272 + nl * 16, g_al + ga); \
        } }

    OLD(0, 0); CPCOMMIT();
    for (int kc = 0; kc < 8; kc++) {
        CPWAIT(); __syncthreads();
        if (kc < 7) { OLD((kc + 1) & 1, kc + 1); CPCOMMIT(); }
        mma_rArB(smem + (kc & 1) * 37888, wm, wn, acc);
    }

    // Cs holds outT: row = g_rel, col = m_rel
    EPI_TO_CS();
    const float* Cs = (const float*)smem;
    #pragma unroll
    for (int it = 0; it < 8; it++) {
        int p = tid + it * 256;
        int gr = p >> 4, nl = p & 15;
        int n = n0 + nl, bb = n >> 9, l = n & 511;
        float4 o1 = *(const float4*)(Cs + gr * 132 + nl * 8);
        float4 o2 = *(const float4*)(Cs + gr * 132 + nl * 8 + 4);
        size_t e = ((size_t)(bb * 8 + c) * 512 + l) * 2048 + (size_t)(g0 + gr) * 8;
        *(float4*)(out + e)     = o1;
        *(float4*)(out + e + 4) = o2;
    }
}

// ============================================================
extern "C" void kernel_launch(void* const* d_in, const int* in_sizes, int n_in,
                              void* d_out, int out_size) {
    const float* x    = (const float*)d_in[0];
    const float* prev = (const float*)d_in[1];
    const float* cw_q = (const float*)d_in[2];
    const float* cw_k = (const float*)d_in[3];
    const float* cw_v = (const float*)d_in[4];
    const float* wq   = (const float*)d_in[5];
    const float* wk   = (const float*)d_in[6];
    const float* wv   = (const float*)d_in[7];
    const float* wo   = (const float*)d_in[8];
    float* out    = (float*)d_out;
    float* qk_out = out + (size_t)NCF;

    cudaFuncSetAttribute(qkv_wm, cudaFuncAttributeMaxDynamicSharedMemorySize, QKV_SMEM);
    cudaFuncSetAttribute(olin_wm, cudaFuncAttributeMaxDynamicSharedMemorySize, QKV_SMEM);
    cudaFuncSetAttribute(qk_wm,   cudaFuncAttributeMaxDynamicSharedMemorySize, QK_SMEM);
    cudaFuncSetAttribute(pv_wm,   cudaFuncAttributeMaxDynamicSharedMemorySize, PV_SMEM);

    prep_w<<<8192, 256>>>(wq, wk, wv, wo);
    conv3_kernel<<<dim3(1024, 4), 256>>>(x, cw_q, cw_k, cw_v);
    qkv_wm<<<dim3(64, 2, 24), 256, QKV_SMEM>>>();
    rope_kernel<<<4096, 256>>>();
    qk_wm<<<dim3(4, 4, 128), 256, QK_SMEM>>>(prev, qk_out);
    stats_kernel<<<65536, 128>>>(qk_out);
    pv_wm<<<dim3(2, 4, 128), 256, PV_SMEM>>>(qk_out);
    olin_wm<<<dim3(64, 2, 8), 256, QKV_SMEM>>>(out);
}

// round 7
// speedup vs baseline: 2.1652x; 1.0168x over previous
#include <cuda_runtime.h>
#include <cuda_bf16.h>
#include <mma.h>
#include <math.h>
#include <cstdint>

using namespace nvcuda;
typedef __nv_bfloat16 bf16;

#define C    8
#define L    512
#define NCF  (1024*8*2048)     // 16,777,216
#define LL   (512*512)

// ---- bf16 hi/lo scratch ----
__device__ bf16 g_c0h[NCF], g_c0l[NCF];
__device__ bf16 g_c1h[NCF], g_c1l[NCF];
__device__ bf16 g_c2h[NCF], g_c2l[NCF];
__device__ bf16 g_qh[NCF],  g_ql[NCF];
__device__ bf16 g_kh[NCF],  g_kl[NCF];
__device__ bf16 g_vh[NCF],  g_vl[NCF];
__device__ bf16 g_ah[NCF],  g_al[NCF];
__device__ bf16 g_wh[4*C*65536], g_wl[4*C*65536];
__device__ float g_rmax[65536], g_rsum[65536];

// ---- helpers ----
__device__ __forceinline__ uint32_t s2u(const void* p) {
    return (uint32_t)__cvta_generic_to_shared(p);
}
__device__ __forceinline__ void cpa16(uint32_t s, const void* g) {
    asm volatile("cp.async.cg.shared.global [%0], [%1], 16;" :: "r"(s), "l"(g));
}
#define CPCOMMIT() asm volatile("cp.async.commit_group;" ::: "memory")
#define CPWAIT()   asm volatile("cp.async.wait_group 0;" ::: "memory")

__device__ __forceinline__ void bsplit(float x, bf16& h, bf16& l) {
    h = __float2bfloat16(x);
    l = __float2bfloat16(x - __bfloat162float(h));
}
__device__ __forceinline__ uint32_t packbf2(bf16 a, bf16 b) {
    __nv_bfloat162 t; t.x = a; t.y = b;
    return *(uint32_t*)&t;
}
__device__ __forceinline__ void pack8(const float* v, uint4& H, uint4& Lo) {
    bf16 h[8], l[8];
    #pragma unroll
    for (int i = 0; i < 8; i++) bsplit(v[i], h[i], l[i]);
    H  = make_uint4(packbf2(h[0],h[1]), packbf2(h[2],h[3]), packbf2(h[4],h[5]), packbf2(h[6],h[7]));
    Lo = make_uint4(packbf2(l[0],l[1]), packbf2(l[2],l[3]), packbf2(l[4],l[5]), packbf2(l[6],l[7]));
}

typedef wmma::fragment<wmma::accumulator, 16, 16, 16, float> AccFrag;

// stage layouts (bytes), per 37888/40960-byte buffer:
//  qk  : Qh 0 (10240) Ql 10240 Kh 20480 Kl 30720   [all K-major 128x40, ldm 40]
//  qkv : Wh 0 (10240) Wl 10240 ATh 20480 (8704) ATl 29184  [AT: 32x136, ldm 136]
//  pv  : Ph 0 (10240) Pl 10240 Vh 20480 (8704) Vl 29184    [V: k x d, ldm 136]

// A row_major K-major (ldm 40); B col_major K-major (ldm 40)
__device__ __forceinline__ void mma_rAcB(const char* buf, int wm, int wn, AccFrag (&acc)[4][2]) {
    const bf16* Ah = (const bf16*)(buf);
    const bf16* Al = (const bf16*)(buf + 10240);
    const bf16* Bh = (const bf16*)(buf + 20480);
    const bf16* Bl = (const bf16*)(buf + 30720);
    #pragma unroll
    for (int ks = 0; ks < 2; ks++) {
        wmma::fragment<wmma::matrix_b, 16, 16, 16, bf16, wmma::col_major> bh[2], bl[2];
        #pragma unroll
        for (int j = 0; j < 2; j++) {
            int n_off = wn * 32 + j * 16;
            wmma::load_matrix_sync(bh[j], Bh + n_off * 40 + ks * 16, 40);
            wmma::load_matrix_sync(bl[j], Bl + n_off * 40 + ks * 16, 40);
        }
        #pragma unroll
        for (int i = 0; i < 4; i++) {
            int m_off = wm * 64 + i * 16;
            wmma::fragment<wmma::matrix_a, 16, 16, 16, bf16, wmma::row_major> ah, al;
            wmma::load_matrix_sync(ah, Ah + m_off * 40 + ks * 16, 40);
            wmma::load_matrix_sync(al, Al + m_off * 40 + ks * 16, 40);
            #pragma unroll
            for (int j = 0; j < 2; j++) {
                wmma::mma_sync(acc[i][j], ah, bh[j], acc[i][j]);
                wmma::mma_sync(acc[i][j], al, bh[j], acc[i][j]);
                wmma::mma_sync(acc[i][j], ah, bl[j], acc[i][j]);
            }
        }
    }
}

// A row_major K-major (ldm 40); B row_major [k][n] (ldm 136)
__device__ __forceinline__ void mma_rArB(const char* buf, int wm, int wn, AccFrag (&acc)[4][2]) {
    const bf16* Ah = (const bf16*)(buf);
    const bf16* Al = (const bf16*)(buf + 10240);
    const bf16* Bh = (const bf16*)(buf + 20480);
    const bf16* Bl = (const bf16*)(buf + 29184);
    #pragma unroll
    for (int ks = 0; ks < 2; ks++) {
        wmma::fragment<wmma::matrix_b, 16, 16, 16, bf16, wmma::row_major> bh[2], bl[2];
        #pragma unroll
        for (int j = 0; j < 2; j++) {
            int n_off = wn * 32 + j * 16;
            wmma::load_matrix_sync(bh[j], Bh + (ks * 16) * 136 + n_off, 136);
            wmma::load_matrix_sync(bl[j], Bl + (ks * 16) * 136 + n_off, 136);
        }
        #pragma unroll
        for (int i = 0; i < 4; i++) {
            int m_off = wm * 64 + i * 16;
            wmma::fragment<wmma::matrix_a, 16, 16, 16, bf16, wmma::row_major> ah, al;
            wmma::load_matrix_sync(ah, Ah + m_off * 40 + ks * 16, 40);
            wmma::load_matrix_sync(al, Al + m_off * 40 + ks * 16, 40);
            #pragma unroll
            for (int j = 0; j < 2; j++) {
                wmma::mma_sync(acc[i][j], ah, bh[j], acc[i][j]);
                wmma::mma_sync(acc[i][j], al, bh[j], acc[i][j]);
                wmma::mma_sync(acc[i][j], ah, bl[j], acc[i][j]);
            }
        }
    }
}

#define DECL_ACC() \
    AccFrag acc[4][2]; \
    _Pragma("unroll") for (int i_ = 0; i_ < 4; i_++) \
        _Pragma("unroll") for (int j_ = 0; j_ < 2; j_++) wmma::fill_fragment(acc[i_][j_], 0.0f);

#define EPI_TO_CS() \
    __syncthreads(); \
    { float* Cs_ = (float*)smem; \
      _Pragma("unroll") for (int i_ = 0; i_ < 4; i_++) \
        _Pragma("unroll") for (int j_ = 0; j_ < 2; j_++) \
          wmma::store_matrix_sync(Cs_ + (wm*64 + i_*16)*132 + wn*32 + j_*16, acc[i_][j_], 132, wmma::mem_row_major); } \
    __syncthreads();

// ============================================================
// prep_w: split 4 weight tensors to bf16 hi/lo.  grid 8192 x 256.
// ============================================================
__global__ void prep_w(const float* __restrict__ wq, const float* __restrict__ wk,
                       const float* __restrict__ wv, const float* __restrict__ wo) {
    int idx = blockIdx.x * 256 + threadIdx.x;
    int t = idx >> 19, off = idx & 524287;
    const float* src = (t == 0) ? wq : (t == 1) ? wk : (t == 2) ? wv : wo;
    bf16 h, l;
    bsplit(src[off], h, l);
    g_wh[idx] = h; g_wl[idx] = l;
}

// ============================================================
// conv3: fused 3x conv3x3 -> bf16 hi/lo outputs [n][c][h*8+w]
// ============================================================
__global__ void conv3_kernel(const float* __restrict__ x,
                             const float* __restrict__ wq,
                             const float* __restrict__ wk,
                             const float* __restrict__ wv) {
    __shared__ float xt[8*66*10];
    __shared__ float wsm[3*576];
    const int n  = blockIdx.x;
    const int y0 = blockIdx.y * 64;
    const int b  = n >> 9, l = n & 511;
    const int tid = threadIdx.x;

    for (int i = tid; i < 576; i += 256) {
        wsm[i] = wq[i]; wsm[576 + i] = wk[i]; wsm[1152 + i] = wv[i];
    }
    for (int i = tid; i < 8*66*10; i += 256) {
        int ci = i / 660, rem = i % 660;
        int yy = rem / 10, xx = rem % 10;
        int y = y0 + yy - 1, xc = xx - 1;
        float v = 0.f;
        if (y >= 0 && y < 256 && xc >= 0 && xc < 8)
            v = x[(((size_t)(b*C + ci)*L + l)*256 + y)*8 + xc];
        xt[i] = v;
    }
    __syncthreads();

    const int yb = tid >> 3, w = tid & 7;
    float acc[2][24];
    #pragma unroll
    for (int r = 0; r < 2; r++)
        #pragma unroll
        for (int o = 0; o < 24; o++) acc[r][o] = 0.f;

    for (int ci = 0; ci < 8; ci++) {
        float xv[2][9];
        #pragma unroll
        for (int r = 0; r < 2; r++)
            #pragma unroll
            for (int ky = 0; ky < 3; ky++)
                #pragma unroll
                for (int kx = 0; kx < 3; kx++)
                    xv[r][ky*3 + kx] = xt[ci*660 + (yb + r*32 + ky)*10 + (w + kx)];
        #pragma unroll
        for (int o = 0; o < 24; o++) {
            int p = o >> 3, co = o & 7;
            const float* wp = &wsm[p*576 + (co*8 + ci)*9];
            #pragma unroll
            for (int k9 = 0; k9 < 9; k9++) {
                float ww = wp[k9];
                acc[0][o] += xv[0][k9] * ww;
                acc[1][o] += xv[1][k9] * ww;
            }
        }
    }
    #pragma unroll
    for (int p = 0; p < 3; p++) {
        bf16* oh = (p == 0) ? g_c0h : (p == 1) ? g_c1h : g_c2h;
        bf16* ol = (p == 0) ? g_c0l : (p == 1) ? g_c1l : g_c2l;
        #pragma unroll
        for (int co = 0; co < 8; co++)
            #pragma unroll
            for (int r = 0; r < 2; r++) {
                size_t off = (size_t)n*16384 + co*2048 + (size_t)(y0 + yb + r*32)*8 + w;
                bf16 hh, lv;
                bsplit(acc[r][p*8 + co], hh, lv);
                oh[off] = hh; ol[off] = lv;
            }
    }
}

// ============================================================
// qkv_wm: 3 projections, transposed: outT[g][m] = W[g][:].AT[:][m]
// RoPE fused into the epilogue for q/k rows with (g&31)<4.
// grid (64, 2, 24), block 256, 2 CTAs/SM.
// ============================================================
#define QKV_SMEM 75776
__global__ void __launch_bounds__(256, 2)
qkv_wm() {
    extern __shared__ __align__(16) char smem[];
    const uint32_t sb = s2u(smem);
    const int tid = threadIdx.x, wid = tid >> 5;
    const int wm = wid >> 2, wn = wid & 3;
    const int c = blockIdx.z & 7, proj = blockIdx.z >> 3;
    const int m0 = blockIdx.x * 128, g0 = blockIdx.y * 128, n0 = m0 >> 3;
    const bf16* Ah_g = (proj == 0) ? g_c0h : (proj == 1) ? g_c1h : g_c2h;
    const bf16* Al_g = (proj == 0) ? g_c0l : (proj == 1) ? g_c1l : g_c2l;
    const bf16* Wh_g = g_wh + (size_t)proj * 524288;
    const bf16* Wl_g = g_wl + (size_t)proj * 524288;
    bf16* Oh = (proj == 0) ? g_qh : (proj == 1) ? g_kh : g_vh;
    bf16* Ol = (proj == 0) ? g_ql : (proj == 1) ? g_kl : g_vl;

    DECL_ACC();

    #define QKVLD(s, kc) { \
        uint32_t sbase = sb + (s) * 37888; int k0 = (kc) * 32; \
        _Pragma("unroll") for (int i = 0; i < 2; i++) { \
            int ch = tid + i * 256; \
            int gr = ch >> 2, c4 = ch & 3; \
            size_t gb = (size_t)c * 65536 + (size_t)(g0 + gr) * 256 + k0 + c4 * 8; \
            cpa16(sbase + gr * 80 + c4 * 16,         Wh_g + gb); \
            cpa16(sbase + 10240 + gr * 80 + c4 * 16, Wl_g + gb); \
            int hr = ch >> 4, nl = ch & 15; \
            size_t ga = (size_t)(n0 + nl) * 16384 + c * 2048 + (size_t)(k0 + hr) * 8; \
            cpa16(sbase + 20480 + hr * 272 + nl * 16, Ah_g + ga); \
            cpa16(sbase + 29184 + hr * 272 + nl * 16, Al_g + ga); \
        } }

    QKVLD(0, 0); CPCOMMIT();
    for (int kc = 0; kc < 8; kc++) {
        CPWAIT(); __syncthreads();
        if (kc < 7) { QKVLD((kc + 1) & 1, kc + 1); CPCOMMIT(); }
        mma_rArB(smem + (kc & 1) * 37888, wm, wn, acc);
    }

    // Cs holds outT: row = g_rel, col = m_rel = (n-n0)*8 + w
    EPI_TO_CS();
    const float* Cs = (const float*)smem;
    #pragma unroll
    for (int it = 0; it < 8; it++) {
        int p = tid + it * 256;
        int gr = p >> 4, nl = p & 15;
        const float* src = Cs + gr * 132 + nl * 8;
        float v[8];
        #pragma unroll
        for (int w = 0; w < 8; w++) v[w] = src[w];
        // fused RoPE: q/k projections, head-dims d = (g&31)*8 + w < 32
        int g = g0 + gr;
        if (proj < 2 && (g & 31) < 4) {
            int l = (n0 + nl) & 511;
            int jb = (g & 31) * 4;
            #pragma unroll
            for (int t = 0; t < 4; t++) {
                float invf = exp2f(-(float)(jb + t) * (13.287712379549449f / 16.0f));
                float sn, cn;
                sincosf((float)l * invf, &sn, &cn);
                float a = v[2*t], bq = v[2*t+1];
                v[2*t]   = a * cn - bq * sn;
                v[2*t+1] = bq * cn + a * sn;
            }
        }
        uint4 H, Lo;
        pack8(v, H, Lo);
        size_t e = (size_t)(n0 + nl) * 16384 + (size_t)c * 2048 + (size_t)g * 8;
        *(uint4*)(Oh + e) = H;
        *(uint4*)(Ol + e) = Lo;
    }
}

// ============================================================
// qk_wm: grid (4, 4, 128), block 256, 2 CTAs/SM.
// ============================================================
#define QK_SMEM 81920
__global__ void __launch_bounds__(256, 2)
qk_wm(const float* __restrict__ prev, float* __restrict__ qk) {
    extern __shared__ __align__(16) char smem[];
    const uint32_t sb = s2u(smem);
    const int tid = threadIdx.x, wid = tid >> 5;
    const int wm = wid >> 2, wn = wid & 3;
    const int z = blockIdx.z;
    const int b = z >> 6, c = (z >> 3) & 7, nh = z & 7;
    const int l0 = blockIdx.y * 128, m0 = blockIdx.x * 128;
    const size_t coff = (size_t)c * 2048 + nh * 256;
    const size_t bL = (size_t)b * 512;

    DECL_ACC();

    #define QKLD(s, kc) { \
        uint32_t sbase = sb + (s) * 40960; int k0 = (kc) * 32; \
        _Pragma("unroll") for (int i = 0; i < 2; i++) { \
            int ch = tid + i * 256; \
            int r = ch >> 2, c4 = ch & 3; \
            uint32_t so = r * 80 + c4 * 16; \
            size_t ga = (bL + l0 + r) * 16384 + coff + k0 + c4 * 8; \
            size_t gb = (bL + m0 + r) * 16384 + coff + k0 + c4 * 8; \
            cpa16(sbase + so,         g_qh + ga); \
            cpa16(sbase + 10240 + so, g_ql + ga); \
            cpa16(sbase + 20480 + so, g_kh + gb); \
            cpa16(sbase + 30720 + so, g_kl + gb); \
        } }

    QKLD(0, 0); CPCOMMIT();
    for (int kc = 0; kc < 8; kc++) {
        CPWAIT(); __syncthreads();
        if (kc < 7) { QKLD((kc + 1) & 1, kc + 1); CPCOMMIT(); }
        mma_rAcB(smem + (kc & 1) * 40960, wm, wn, acc);
    }

    EPI_TO_CS();
    const float* Cs = (const float*)smem;
    const int col = tid & 127;
    #pragma unroll 4
    for (int jj = 0; jj < 64; jj++) {
        int r = jj * 2 + (tid >> 7);
        size_t idx = (size_t)z * LL + (size_t)(l0 + r) * 512 + m0 + col;
        qk[idx] = Cs[r * 132 + col] * 0.0625f + prev[idx];
    }
}

// ============================================================
// stats: per-row max + sumexp. grid 65536 x 128.
// ============================================================
__global__ void stats_kernel(const float* __restrict__ qk) {
    const int row = blockIdx.x;
    const int tid = threadIdx.x;
    const float4 v = reinterpret_cast<const float4*>(qk + (size_t)row*512)[tid];
    float mx = fmaxf(fmaxf(v.x, v.y), fmaxf(v.z, v.w));
    #pragma unroll
    for (int o = 16; o; o >>= 1) mx = fmaxf(mx, __shfl_xor_sync(~0u, mx, o));
    __shared__ float sm[4], ss[4];
    if ((tid & 31) == 0) sm[tid >> 5] = mx;
    __syncthreads();
    mx = fmaxf(fmaxf(sm[0], sm[1]), fmaxf(sm[2], sm[3]));
    float s = expf(v.x - mx) + expf(v.y - mx) + expf(v.z - mx) + expf(v.w - mx);
    #pragma unroll
    for (int o = 16; o; o >>= 1) s += __shfl_xor_sync(~0u, s, o);
    if ((tid & 31) == 0) ss[tid >> 5] = s;
    __syncthreads();
    if (tid == 0) {
        g_rmax[row] = mx;
        g_rsum[row] = ss[0] + ss[1] + ss[2] + ss[3];
    }
}

// ============================================================
// pv_wm: grid (2, 4, 128), block 256, 2 CTAs/SM. K=512, 16 chunks.
// Single barrier per chunk: P(kc+1) staged into the opposite buffer
// right after the barrier (its last reader MMA(kc-1) is done by then).
// ============================================================
#define PV_SMEM 76800
__global__ void __launch_bounds__(256, 2)
pv_wm(const float* __restrict__ qkv) {
    extern __shared__ __align__(16) char smem[];
    const uint32_t sb = s2u(smem);
    const int tid = threadIdx.x, wid = tid >> 5;
    const int wm = wid >> 2, wn = wid & 3;
    const int z = blockIdx.z;
    const int b = z >> 6, c = (z >> 3) & 7, nh = z & 7;
    const int l0 = blockIdx.y * 128, d0 = blockIdx.x * 128;
    const size_t coff = (size_t)c * 2048 + nh * 256;
    const size_t bL = (size_t)b * 512;
    float* rinv = (float*)(smem + 75776);
    float* rmx  = (float*)(smem + 76288);
    if (tid < 128) {
        rmx[tid]  = g_rmax[z * 512 + l0 + tid];
        rinv[tid] = 1.0f / g_rsum[z * 512 + l0 + tid];
    }
    __syncthreads();

    DECL_ACC();
    float4 ra[4];
    const int rl = tid >> 3, d4 = tid & 7;

    #define PVARLD(kc) { int k0 = (kc) * 32; \
        _Pragma("unroll") for (int it = 0; it < 4; it++) \
            ra[it] = *(const float4*)(qkv + (size_t)z * LL + (size_t)(l0 + rl + it * 32) * 512 + k0 + d4 * 4); }

    #define PVASTS(s) { char* buf = smem + (s) * 37888; \
        _Pragma("unroll") for (int it = 0; it < 4; it++) { \
            int r = rl + it * 32; \
            float mx = rmx[r]; \
            float e0 = __expf(ra[it].x - mx), e1 = __expf(ra[it].y - mx); \
            float e2 = __expf(ra[it].z - mx), e3 = __expf(ra[it].w - mx); \
            bf16 h0, lo0, h1, lo1, h2, lo2, h3, lo3; \
            bsplit(e0, h0, lo0); bsplit(e1, h1, lo1); \
            bsplit(e2, h2, lo2); bsplit(e3, h3, lo3); \
            *(uint2*)(buf + r * 80 + d4 * 8)         = make_uint2(packbf2(h0, h1), packbf2(h2, h3)); \
            *(uint2*)(buf + 10240 + r * 80 + d4 * 8) = make_uint2(packbf2(lo0, lo1), packbf2(lo2, lo3)); \
        } }

    #define PVBLD(s, kc) { uint32_t sbase = sb + (s) * 37888; int k0 = (kc) * 32; \
        _Pragma("unroll") for (int i = 0; i < 2; i++) { \
            int ch = tid + i * 256; \
            int mr = ch >> 4, d8 = ch & 15; \
            size_t g = (bL + k0 + mr) * 16384 + coff + d0 + d8 * 8; \
            cpa16(sbase + 20480 + mr * 272 + d8 * 16, g_vh + g); \
            cpa16(sbase + 29184 + mr * 272 + d8 * 16, g_vl + g); \
        } }

    PVARLD(0);
    PVASTS(0);                         // P(0) -> buf0 (no prior readers)
    PVBLD(0, 0); CPCOMMIT();           // V(0) -> buf0
    PVARLD(1);                         // regs: chunk 1
    for (int kc = 0; kc < 16; kc++) {
        CPWAIT(); __syncthreads();     // V(kc) visible; MMA(kc-1) done -> buf (kc+1)&1 free
        if (kc < 15) {
            PVASTS((kc + 1) & 1);      // P(kc+1) from ra
            PVBLD((kc + 1) & 1, kc + 1); CPCOMMIT();
            if (kc < 14) PVARLD(kc + 2);
        }
        mma_rArB(smem + (kc & 1) * 37888, wm, wn, acc);
    }

    EPI_TO_CS();
    const float* Cs = (const float*)smem;
    #pragma unroll
    for (int it = 0; it < 8; it++) {
        int r = (tid >> 4) + it * 16;
        int col8 = (tid & 15) * 8;
        float4 a1 = *(const float4*)(Cs + r * 132 + col8);
        float4 a2 = *(const float4*)(Cs + r * 132 + col8 + 4);
        float iv = rinv[r];
        float v[8] = {a1.x*iv, a1.y*iv, a1.z*iv, a1.w*iv, a2.x*iv, a2.y*iv, a2.z*iv, a2.w*iv};
        uint4 H, Lo;
        pack8(v, H, Lo);
        size_t e = (bL + l0 + r) * 16384 + coff + d0 + col8;
        *(uint4*)(g_ah + e) = H;
        *(uint4*)(g_al + e) = Lo;
    }
}

// ============================================================
// olin_wm: wo projection, transposed formulation. -> f32 out.
// ============================================================
__global__ void __launch_bounds__(256, 2)
olin_wm(float* __restrict__ out) {
    extern __shared__ __align__(16) char smem[];
    const uint32_t sb = s2u(smem);
    const int tid = threadIdx.x, wid = tid >> 5;
    const int wm = wid >> 2, wn = wid & 3;
    const int c = blockIdx.z, m0 = blockIdx.x * 128, g0 = blockIdx.y * 128, n0 = m0 >> 3;
    const bf16* Wh_g = g_wh + (size_t)3 * 524288;
    const bf16* Wl_g = g_wl + (size_t)3 * 524288;

    DECL_ACC();

    #define OLD(s, kc) { \
        uint32_t sbase = sb + (s) * 37888; int k0 = (kc) * 32; \
        _Pragma("unroll") for (int i = 0; i < 2; i++) { \
            int ch = tid + i * 256; \
            int gr = ch >> 2, c4 = ch & 3; \
            size_t gb = (size_t)c * 65536 + (size_t)(g0 + gr) * 256 + k0 + c4 * 8; \
            cpa16(sbase + gr * 80 + c4 * 16,         Wh_g + gb); \
            cpa16(sbase + 10240 + gr * 80 + c4 * 16, Wl_g + gb); \
            int hr = ch >> 4, nl = ch & 15; \
            size_t ga = (size_t)(n0 + nl) * 16384 + c * 2048 + (size_t)(k0 + hr) * 8; \
            cpa16(sbase + 20480 + hr * 272 + nl * 16, g_ah + ga); \
            cpa16(sbase + 29184 + hr * 272 + nl * 16, g_al + ga); \
        } }

    OLD(0, 0); CPCOMMIT();
    for (int kc = 0; kc < 8; kc++) {
        CPWAIT(); __syncthreads();
        if (kc < 7) { OLD((kc + 1) & 1, kc + 1); CPCOMMIT(); }
        mma_rArB(smem + (kc & 1) * 37888, wm, wn, acc);
    }

    EPI_TO_CS();
    const float* Cs = (const float*)smem;
    #pragma unroll
    for (int it = 0; it < 8; it++) {
        int p = tid + it * 256;
        int gr = p >> 4, nl = p & 15;
        int n = n0 + nl, bb = n >> 9, l = n & 511;
        float4 o1 = *(const float4*)(Cs + gr * 132 + nl * 8);
        float4 o2 = *(const float4*)(Cs + gr * 132 + nl * 8 + 4);
        size_t e = ((size_t)(bb * 8 + c) * 512 + l) * 2048 + (size_t)(g0 + gr) * 8;
        *(float4*)(out + e)     = o1;
        *(float4*)(out + e + 4) = o2;
    }
}

// ============================================================
extern "C" void kernel_launch(void* const* d_in, const int* in_sizes, int n_in,
                              void* d_out, int out_size) {
    const float* x    = (const float*)d_in[0];
    const float* prev = (const float*)d_in[1];
    const float* cw_q = (const float*)d_in[2];
    const float* cw_k = (const float*)d_in[3];
    const float* cw_v = (const float*)d_in[4];
    const float* wq   = (const float*)d_in[5];
    const float* wk   = (const float*)d_in[6];
    const float* wv   = (const float*)d_in[7];
    const float* wo   = (const float*)d_in[8];
    float* out    = (float*)d_out;
    float* qk_out = out + (size_t)NCF;

    cudaFuncSetAttribute(qkv_wm, cudaFuncAttributeMaxDynamicSharedMemorySize, QKV_SMEM);
    cudaFuncSetAttribute(olin_wm, cudaFuncAttributeMaxDynamicSharedMemorySize, QKV_SMEM);
    cudaFuncSetAttribute(qk_wm,   cudaFuncAttributeMaxDynamicSharedMemorySize, QK_SMEM);
    cudaFuncSetAttribute(pv_wm,   cudaFuncAttributeMaxDynamicSharedMemorySize, PV_SMEM);

    prep_w<<<8192, 256>>>(wq, wk, wv, wo);
    conv3_kernel<<<dim3(1024, 4), 256>>>(x, cw_q, cw_k, cw_v);
    qkv_wm<<<dim3(64, 2, 24), 256, QKV_SMEM>>>();
    qk_wm<<<dim3(4, 4, 128), 256, QK_SMEM>>>(prev, qk_out);
    stats_kernel<<<65536, 128>>>(qk_out);
    pv_wm<<<dim3(2, 4, 128), 256, PV_SMEM>>>(qk_out);
    olin_wm<<<dim3(64, 2, 8), 256, QKV_SMEM>>>(out);
}

// round 8
// speedup vs baseline: 2.2014x; 1.0167x over previous
#include <cuda_runtime.h>
#include <cuda_bf16.h>
#include <mma.h>
#include <math.h>
#include <cstdint>

using namespace nvcuda;
typedef __nv_bfloat16 bf16;

#define C    8
#define L    512
#define NCF  (1024*8*2048)     // 16,777,216
#define LL   (512*512)

// ---- bf16 hi/lo scratch ----
__device__ bf16 g_c0h[NCF], g_c0l[NCF];
__device__ bf16 g_c1h[NCF], g_c1l[NCF];
__device__ bf16 g_c2h[NCF], g_c2l[NCF];
__device__ bf16 g_qh[NCF],  g_ql[NCF];
__device__ bf16 g_kh[NCF],  g_kl[NCF];
__device__ bf16 g_vh[NCF],  g_vl[NCF];
__device__ bf16 g_ah[NCF],  g_al[NCF];
__device__ bf16 g_wh[4*C*65536], g_wl[4*C*65536];
__device__ float g_rmax[65536], g_rsum[65536];

// ---- helpers ----
__device__ __forceinline__ uint32_t s2u(const void* p) {
    return (uint32_t)__cvta_generic_to_shared(p);
}
__device__ __forceinline__ void cpa16(uint32_t s, const void* g) {
    asm volatile("cp.async.cg.shared.global [%0], [%1], 16;" :: "r"(s), "l"(g));
}
#define CPCOMMIT() asm volatile("cp.async.commit_group;" ::: "memory")
#define CPWAIT()   asm volatile("cp.async.wait_group 0;" ::: "memory")
#define CPWAIT1()  asm volatile("cp.async.wait_group 1;" ::: "memory")

__device__ __forceinline__ void bsplit(float x, bf16& h, bf16& l) {
    h = __float2bfloat16(x);
    l = __float2bfloat16(x - __bfloat162float(h));
}
__device__ __forceinline__ uint32_t packbf2(bf16 a, bf16 b) {
    __nv_bfloat162 t; t.x = a; t.y = b;
    return *(uint32_t*)&t;
}
__device__ __forceinline__ void pack8(const float* v, uint4& H, uint4& Lo) {
    bf16 h[8], l[8];
    #pragma unroll
    for (int i = 0; i < 8; i++) bsplit(v[i], h[i], l[i]);
    H  = make_uint4(packbf2(h[0],h[1]), packbf2(h[2],h[3]), packbf2(h[4],h[5]), packbf2(h[6],h[7]));
    Lo = make_uint4(packbf2(l[0],l[1]), packbf2(l[2],l[3]), packbf2(l[4],l[5]), packbf2(l[6],l[7]));
}

typedef wmma::fragment<wmma::accumulator, 16, 16, 16, float> AccFrag;

// stage layouts (bytes), per stage:
//  qk  (40960): Qh 0  Ql 10240  Kh 20480  Kl 30720   [K-major 128x40, ldm 40]
//  qkv (37888): Wh 0  Wl 10240  ATh 20480 ATl 29184  [AT: 32x136, ldm 136]
//  pv  (37888): Ph 0  Pl 10240  Vh 20480  Vl 29184   [V: k x d, ldm 136]

// A row_major K-major (ldm 40); B col_major K-major (ldm 40)
__device__ __forceinline__ void mma_rAcB(const char* buf, int wm, int wn, AccFrag (&acc)[4][2]) {
    const bf16* Ah = (const bf16*)(buf);
    const bf16* Al = (const bf16*)(buf + 10240);
    const bf16* Bh = (const bf16*)(buf + 20480);
    const bf16* Bl = (const bf16*)(buf + 30720);
    #pragma unroll
    for (int ks = 0; ks < 2; ks++) {
        wmma::fragment<wmma::matrix_b, 16, 16, 16, bf16, wmma::col_major> bh[2], bl[2];
        #pragma unroll
        for (int j = 0; j < 2; j++) {
            int n_off = wn * 32 + j * 16;
            wmma::load_matrix_sync(bh[j], Bh + n_off * 40 + ks * 16, 40);
            wmma::load_matrix_sync(bl[j], Bl + n_off * 40 + ks * 16, 40);
        }
        #pragma unroll
        for (int i = 0; i < 4; i++) {
            int m_off = wm * 64 + i * 16;
            wmma::fragment<wmma::matrix_a, 16, 16, 16, bf16, wmma::row_major> ah, al;
            wmma::load_matrix_sync(ah, Ah + m_off * 40 + ks * 16, 40);
            wmma::load_matrix_sync(al, Al + m_off * 40 + ks * 16, 40);
            #pragma unroll
            for (int j = 0; j < 2; j++) {
                wmma::mma_sync(acc[i][j], ah, bh[j], acc[i][j]);
                wmma::mma_sync(acc[i][j], al, bh[j], acc[i][j]);
                wmma::mma_sync(acc[i][j], ah, bl[j], acc[i][j]);
            }
        }
    }
}

// A row_major K-major (ldm 40); B row_major [k][n] (ldm 136)
__device__ __forceinline__ void mma_rArB(const char* buf, int wm, int wn, AccFrag (&acc)[4][2]) {
    const bf16* Ah = (const bf16*)(buf);
    const bf16* Al = (const bf16*)(buf + 10240);
    const bf16* Bh = (const bf16*)(buf + 20480);
    const bf16* Bl = (const bf16*)(buf + 29184);
    #pragma unroll
    for (int ks = 0; ks < 2; ks++) {
        wmma::fragment<wmma::matrix_b, 16, 16, 16, bf16, wmma::row_major> bh[2], bl[2];
        #pragma unroll
        for (int j = 0; j < 2; j++) {
            int n_off = wn * 32 + j * 16;
            wmma::load_matrix_sync(bh[j], Bh + (ks * 16) * 136 + n_off, 136);
            wmma::load_matrix_sync(bl[j], Bl + (ks * 16) * 136 + n_off, 136);
        }
        #pragma unroll
        for (int i = 0; i < 4; i++) {
            int m_off = wm * 64 + i * 16;
            wmma::fragment<wmma::matrix_a, 16, 16, 16, bf16, wmma::row_major> ah, al;
            wmma::load_matrix_sync(ah, Ah + m_off * 40 + ks * 16, 40);
            wmma::load_matrix_sync(al, Al + m_off * 40 + ks * 16, 40);
            #pragma unroll
            for (int j = 0; j < 2; j++) {
                wmma::mma_sync(acc[i][j], ah, bh[j], acc[i][j]);
                wmma::mma_sync(acc[i][j], al, bh[j], acc[i][j]);
                wmma::mma_sync(acc[i][j], ah, bl[j], acc[i][j]);
            }
        }
    }
}

#define DECL_ACC() \
    AccFrag acc[4][2]; \
    _Pragma("unroll") for (int i_ = 0; i_ < 4; i_++) \
        _Pragma("unroll") for (int j_ = 0; j_ < 2; j_++) wmma::fill_fragment(acc[i_][j_], 0.0f);

#define EPI_TO_CS() \
    __syncthreads(); \
    { float* Cs_ = (float*)smem; \
      _Pragma("unroll") for (int i_ = 0; i_ < 4; i_++) \
        _Pragma("unroll") for (int j_ = 0; j_ < 2; j_++) \
          wmma::store_matrix_sync(Cs_ + (wm*64 + i_*16)*132 + wn*32 + j_*16, acc[i_][j_], 132, wmma::mem_row_major); } \
    __syncthreads();

// ============================================================
// prep_w: split 4 weight tensors to bf16 hi/lo.  grid 8192 x 256.
// ============================================================
__global__ void prep_w(const float* __restrict__ wq, const float* __restrict__ wk,
                       const float* __restrict__ wv, const float* __restrict__ wo) {
    int idx = blockIdx.x * 256 + threadIdx.x;
    int t = idx >> 19, off = idx & 524287;
    const float* src = (t == 0) ? wq : (t == 1) ? wk : (t == 2) ? wv : wo;
    bf16 h, l;
    bsplit(src[off], h, l);
    g_wh[idx] = h; g_wl[idx] = l;
}

// ============================================================
// conv3: fused 3x conv3x3 -> bf16 hi/lo outputs [n][c][h*8+w]
// ============================================================
__global__ void conv3_kernel(const float* __restrict__ x,
                             const float* __restrict__ wq,
                             const float* __restrict__ wk,
                             const float* __restrict__ wv) {
    __shared__ float xt[8*66*10];
    __shared__ float wsm[3*576];
    const int n  = blockIdx.x;
    const int y0 = blockIdx.y * 64;
    const int b  = n >> 9, l = n & 511;
    const int tid = threadIdx.x;

    for (int i = tid; i < 576; i += 256) {
        wsm[i] = wq[i]; wsm[576 + i] = wk[i]; wsm[1152 + i] = wv[i];
    }
    for (int i = tid; i < 8*66*10; i += 256) {
        int ci = i / 660, rem = i % 660;
        int yy = rem / 10, xx = rem % 10;
        int y = y0 + yy - 1, xc = xx - 1;
        float v = 0.f;
        if (y >= 0 && y < 256 && xc >= 0 && xc < 8)
            v = x[(((size_t)(b*C + ci)*L + l)*256 + y)*8 + xc];
        xt[i] = v;
    }
    __syncthreads();

    const int yb = tid >> 3, w = tid & 7;
    float acc[2][24];
    #pragma unroll
    for (int r = 0; r < 2; r++)
        #pragma unroll
        for (int o = 0; o < 24; o++) acc[r][o] = 0.f;

    for (int ci = 0; ci < 8; ci++) {
        float xv[2][9];
        #pragma unroll
        for (int r = 0; r < 2; r++)
            #pragma unroll
            for (int ky = 0; ky < 3; ky++)
                #pragma unroll
                for (int kx = 0; kx < 3; kx++)
                    xv[r][ky*3 + kx] = xt[ci*660 + (yb + r*32 + ky)*10 + (w + kx)];
        #pragma unroll
        for (int o = 0; o < 24; o++) {
            int p = o >> 3, co = o & 7;
            const float* wp = &wsm[p*576 + (co*8 + ci)*9];
            #pragma unroll
            for (int k9 = 0; k9 < 9; k9++) {
                float ww = wp[k9];
                acc[0][o] += xv[0][k9] * ww;
                acc[1][o] += xv[1][k9] * ww;
            }
        }
    }
    #pragma unroll
    for (int p = 0; p < 3; p++) {
        bf16* oh = (p == 0) ? g_c0h : (p == 1) ? g_c1h : g_c2h;
        bf16* ol = (p == 0) ? g_c0l : (p == 1) ? g_c1l : g_c2l;
        #pragma unroll
        for (int co = 0; co < 8; co++)
            #pragma unroll
            for (int r = 0; r < 2; r++) {
                size_t off = (size_t)n*16384 + co*2048 + (size_t)(y0 + yb + r*32)*8 + w;
                bf16 hh, lv;
                bsplit(acc[r][p*8 + co], hh, lv);
                oh[off] = hh; ol[off] = lv;
            }
    }
}

// ============================================================
// qkv_wm: 3 projections, transposed: outT[g][m] = W[g][:].AT[:][m]
// 3-stage cp.async pipeline (wait_group 1). RoPE fused in epilogue.
// grid (64, 2, 24), block 256, 2 CTAs/SM.
// ============================================================
#define QKV_SMEM 113664
__global__ void __launch_bounds__(256, 2)
qkv_wm() {
    extern __shared__ __align__(16) char smem[];
    const uint32_t sb = s2u(smem);
    const int tid = threadIdx.x, wid = tid >> 5;
    const int wm = wid >> 2, wn = wid & 3;
    const int c = blockIdx.z & 7, proj = blockIdx.z >> 3;
    const int m0 = blockIdx.x * 128, g0 = blockIdx.y * 128, n0 = m0 >> 3;
    const bf16* Ah_g = (proj == 0) ? g_c0h : (proj == 1) ? g_c1h : g_c2h;
    const bf16* Al_g = (proj == 0) ? g_c0l : (proj == 1) ? g_c1l : g_c2l;
    const bf16* Wh_g = g_wh + (size_t)proj * 524288;
    const bf16* Wl_g = g_wl + (size_t)proj * 524288;
    bf16* Oh = (proj == 0) ? g_qh : (proj == 1) ? g_kh : g_vh;
    bf16* Ol = (proj == 0) ? g_ql : (proj == 1) ? g_kl : g_vl;

    DECL_ACC();

    #define QKVLD(s, kc) { \
        uint32_t sbase = sb + (s) * 37888; int k0 = (kc) * 32; \
        _Pragma("unroll") for (int i = 0; i < 2; i++) { \
            int ch = tid + i * 256; \
            int gr = ch >> 2, c4 = ch & 3; \
            size_t gb = (size_t)c * 65536 + (size_t)(g0 + gr) * 256 + k0 + c4 * 8; \
            cpa16(sbase + gr * 80 + c4 * 16,         Wh_g + gb); \
            cpa16(sbase + 10240 + gr * 80 + c4 * 16, Wl_g + gb); \
            int hr = ch >> 4, nl = ch & 15; \
            size_t ga = (size_t)(n0 + nl) * 16384 + c * 2048 + (size_t)(k0 + hr) * 8; \
            cpa16(sbase + 20480 + hr * 272 + nl * 16, Ah_g + ga); \
            cpa16(sbase + 29184 + hr * 272 + nl * 16, Al_g + ga); \
        } }

    QKVLD(0, 0); CPCOMMIT();
    QKVLD(1, 1); CPCOMMIT();
    for (int kc = 0; kc < 8; kc++) {
        if (kc == 7) { CPWAIT(); } else { CPWAIT1(); }
        __syncthreads();
        if (kc < 6) { QKVLD((kc + 2) % 3, kc + 2); CPCOMMIT(); }
        mma_rArB(smem + (kc % 3) * 37888, wm, wn, acc);
    }

    // Cs holds outT: row = g_rel, col = m_rel = (n-n0)*8 + w
    EPI_TO_CS();
    const float* Cs = (const float*)smem;
    #pragma unroll
    for (int it = 0; it < 8; it++) {
        int p = tid + it * 256;
        int gr = p >> 4, nl = p & 15;
        const float* src = Cs + gr * 132 + nl * 8;
        float4 v01 = *(const float4*)(src);
        float4 v23 = *(const float4*)(src + 4);
        float v[8] = {v01.x, v01.y, v01.z, v01.w, v23.x, v23.y, v23.z, v23.w};
        // fused RoPE: q/k projections, head-dims d = (g&31)*8 + w < 32
        int g = g0 + gr;
        if (proj < 2 && (g & 31) < 4) {
            int l = (n0 + nl) & 511;
            int jb = (g & 31) * 4;
            #pragma unroll
            for (int t = 0; t < 4; t++) {
                float invf = exp2f(-(float)(jb + t) * (13.287712379549449f / 16.0f));
                float sn, cn;
                sincosf((float)l * invf, &sn, &cn);
                float a = v[2*t], bq = v[2*t+1];
                v[2*t]   = a * cn - bq * sn;
                v[2*t+1] = bq * cn + a * sn;
            }
        }
        uint4 H, Lo;
        pack8(v, H, Lo);
        size_t e = (size_t)(n0 + nl) * 16384 + (size_t)c * 2048 + (size_t)g * 8;
        *(uint4*)(Oh + e) = H;
        *(uint4*)(Ol + e) = Lo;
    }
}

// ============================================================
// qk_wm: 2-stage pipeline (smem-bound), vectorized epilogue.
// grid (4, 4, 128), block 256, 2 CTAs/SM.
// ============================================================
#define QK_SMEM 81920
__global__ void __launch_bounds__(256, 2)
qk_wm(const float* __restrict__ prev, float* __restrict__ qk) {
    extern __shared__ __align__(16) char smem[];
    const uint32_t sb = s2u(smem);
    const int tid = threadIdx.x, wid = tid >> 5;
    const int wm = wid >> 2, wn = wid & 3;
    const int z = blockIdx.z;
    const int b = z >> 6, c = (z >> 3) & 7, nh = z & 7;
    const int l0 = blockIdx.y * 128, m0 = blockIdx.x * 128;
    const size_t coff = (size_t)c * 2048 + nh * 256;
    const size_t bL = (size_t)b * 512;

    DECL_ACC();

    #define QKLD(s, kc) { \
        uint32_t sbase = sb + (s) * 40960; int k0 = (kc) * 32; \
        _Pragma("unroll") for (int i = 0; i < 2; i++) { \
            int ch = tid + i * 256; \
            int r = ch >> 2, c4 = ch & 3; \
            uint32_t so = r * 80 + c4 * 16; \
            size_t ga = (bL + l0 + r) * 16384 + coff + k0 + c4 * 8; \
            size_t gb = (bL + m0 + r) * 16384 + coff + k0 + c4 * 8; \
            cpa16(sbase + so,         g_qh + ga); \
            cpa16(sbase + 10240 + so, g_ql + ga); \
            cpa16(sbase + 20480 + so, g_kh + gb); \
            cpa16(sbase + 30720 + so, g_kl + gb); \
        } }

    QKLD(0, 0); CPCOMMIT();
    for (int kc = 0; kc < 8; kc++) {
        CPWAIT(); __syncthreads();
        if (kc < 7) { QKLD((kc + 1) & 1, kc + 1); CPCOMMIT(); }
        mma_rAcB(smem + (kc & 1) * 40960, wm, wn, acc);
    }

    EPI_TO_CS();
    const float* Cs = (const float*)smem;
    const int col4 = (tid & 31) * 4;
    const int rb = tid >> 5;
    #pragma unroll
    for (int jj = 0; jj < 16; jj++) {
        int r = rb + jj * 8;
        float4 cv = *(const float4*)(Cs + r * 132 + col4);
        size_t idx = (size_t)z * LL + (size_t)(l0 + r) * 512 + m0 + col4;
        float4 pv = *(const float4*)(prev + idx);
        float4 o;
        o.x = cv.x * 0.0625f + pv.x;
        o.y = cv.y * 0.0625f + pv.y;
        o.z = cv.z * 0.0625f + pv.z;
        o.w = cv.w * 0.0625f + pv.w;
        *(float4*)(qk + idx) = o;
    }
}

// ============================================================
// stats: per-row max + sumexp. grid 65536 x 128.
// ============================================================
__global__ void stats_kernel(const float* __restrict__ qk) {
    const int row = blockIdx.x;
    const int tid = threadIdx.x;
    const float4 v = reinterpret_cast<const float4*>(qk + (size_t)row*512)[tid];
    float mx = fmaxf(fmaxf(v.x, v.y), fmaxf(v.z, v.w));
    #pragma unroll
    for (int o = 16; o; o >>= 1) mx = fmaxf(mx, __shfl_xor_sync(~0u, mx, o));
    __shared__ float sm[4], ss[4];
    if ((tid & 31) == 0) sm[tid >> 5] = mx;
    __syncthreads();
    mx = fmaxf(fmaxf(sm[0], sm[1]), fmaxf(sm[2], sm[3]));
    float s = expf(v.x - mx) + expf(v.y - mx) + expf(v.z - mx) + expf(v.w - mx);
    #pragma unroll
    for (int o = 16; o; o >>= 1) s += __shfl_xor_sync(~0u, s, o);
    if ((tid & 31) == 0) ss[tid >> 5] = s;
    __syncthreads();
    if (tid == 0) {
        g_rmax[row] = mx;
        g_rsum[row] = ss[0] + ss[1] + ss[2] + ss[3];
    }
}

// ============================================================
// pv_wm: 3-stage pipeline, single barrier per chunk.
// grid (2, 4, 128), block 256, 2 CTAs/SM. K=512, 16 chunks.
// ============================================================
#define PV_SMEM 114688
__global__ void __launch_bounds__(256, 2)
pv_wm(const float* __restrict__ qkv) {
    extern __shared__ __align__(16) char smem[];
    const uint32_t sb = s2u(smem);
    const int tid = threadIdx.x, wid = tid >> 5;
    const int wm = wid >> 2, wn = wid & 3;
    const int z = blockIdx.z;
    const int b = z >> 6, c = (z >> 3) & 7, nh = z & 7;
    const int l0 = blockIdx.y * 128, d0 = blockIdx.x * 128;
    const size_t coff = (size_t)c * 2048 + nh * 256;
    const size_t bL = (size_t)b * 512;
    float* rinv = (float*)(smem + 113664);
    float* rmx  = (float*)(smem + 114176);
    if (tid < 128) {
        rmx[tid]  = g_rmax[z * 512 + l0 + tid];
        rinv[tid] = 1.0f / g_rsum[z * 512 + l0 + tid];
    }
    __syncthreads();

    DECL_ACC();
    float4 ra[4];
    const int rl = tid >> 3, d4 = tid & 7;

    #define PVARLD(kc) { int k0 = (kc) * 32; \
        _Pragma("unroll") for (int it = 0; it < 4; it++) \
            ra[it] = *(const float4*)(qkv + (size_t)z * LL + (size_t)(l0 + rl + it * 32) * 512 + k0 + d4 * 4); }

    #define PVASTS(s) { char* buf = smem + (s) * 37888; \
        _Pragma("unroll") for (int it = 0; it < 4; it++) { \
            int r = rl + it * 32; \
            float mx = rmx[r]; \
            float e0 = __expf(ra[it].x - mx), e1 = __expf(ra[it].y - mx); \
            float e2 = __expf(ra[it].z - mx), e3 = __expf(ra[it].w - mx); \
            bf16 h0, lo0, h1, lo1, h2, lo2, h3, lo3; \
            bsplit(e0, h0, lo0); bsplit(e1, h1, lo1); \
            bsplit(e2, h2, lo2); bsplit(e3, h3, lo3); \
            *(uint2*)(buf + r * 80 + d4 * 8)         = make_uint2(packbf2(h0, h1), packbf2(h2, h3)); \
            *(uint2*)(buf + 10240 + r * 80 + d4 * 8) = make_uint2(packbf2(lo0, lo1), packbf2(lo2, lo3)); \
        } }

    #define PVBLD(s, kc) { uint32_t sbase = sb + (s) * 37888; int k0 = (kc) * 32; \
        _Pragma("unroll") for (int i = 0; i < 2; i++) { \
            int ch = tid + i * 256; \
            int mr = ch >> 4, d8 = ch & 15; \
            size_t g = (bL + k0 + mr) * 16384 + coff + d0 + d8 * 8; \
            cpa16(sbase + 20480 + mr * 272 + d8 * 16, g_vh + g); \
            cpa16(sbase + 29184 + mr * 272 + d8 * 16, g_vl + g); \
        } }

    PVARLD(0); PVASTS(0); PVBLD(0, 0); CPCOMMIT();
    PVARLD(1); PVASTS(1); PVBLD(1, 1); CPCOMMIT();
    PVARLD(2);
    for (int kc = 0; kc < 16; kc++) {
        if (kc == 15) { CPWAIT(); } else { CPWAIT1(); }
        __syncthreads();                 // MMA(kc-1) done; buf (kc+2)%3 free
        if (kc < 14) {
            PVASTS((kc + 2) % 3);        // P(kc+2) from ra
            PVBLD((kc + 2) % 3, kc + 2); CPCOMMIT();
            if (kc < 13) PVARLD(kc + 3);
        }
        mma_rArB(smem + (kc % 3) * 37888, wm, wn, acc);
    }

    EPI_TO_CS();
    const float* Cs = (const float*)smem;
    #pragma unroll
    for (int it = 0; it < 8; it++) {
        int r = (tid >> 4) + it * 16;
        int col8 = (tid & 15) * 8;
        float4 a1 = *(const float4*)(Cs + r * 132 + col8);
        float4 a2 = *(const float4*)(Cs + r * 132 + col8 + 4);
        float iv = rinv[r];
        float v[8] = {a1.x*iv, a1.y*iv, a1.z*iv, a1.w*iv, a2.x*iv, a2.y*iv, a2.z*iv, a2.w*iv};
        uint4 H, Lo;
        pack8(v, H, Lo);
        size_t e = (bL + l0 + r) * 16384 + coff + d0 + col8;
        *(uint4*)(g_ah + e) = H;
        *(uint4*)(g_al + e) = Lo;
    }
}

// ============================================================
// olin_wm: wo projection, transposed, 3-stage pipeline. -> f32 out.
// ============================================================
__global__ void __launch_bounds__(256, 2)
olin_wm(float* __restrict__ out) {
    extern __shared__ __align__(16) char smem[];
    const uint32_t sb = s2u(smem);
    const int tid = threadIdx.x, wid = tid >> 5;
    const int wm = wid >> 2, wn = wid & 3;
    const int c = blockIdx.z, m0 = blockIdx.x * 128, g0 = blockIdx.y * 128, n0 = m0 >> 3;
    const bf16* Wh_g = g_wh + (size_t)3 * 524288;
    const bf16* Wl_g = g_wl + (size_t)3 * 524288;

    DECL_ACC();

    #define OLD(s, kc) { \
        uint32_t sbase = sb + (s) * 37888; int k0 = (kc) * 32; \
        _Pragma("unroll") for (int i = 0; i < 2; i++) { \
            int ch = tid + i * 256; \
            int gr = ch >> 2, c4 = ch & 3; \
            size_t gb = (size_t)c * 65536 + (size_t)(g0 + gr) * 256 + k0 + c4 * 8; \
            cpa16(sbase + gr * 80 + c4 * 16,         Wh_g + gb); \
            cpa16(sbase + 10240 + gr * 80 + c4 * 16, Wl_g + gb); \
            int hr = ch >> 4, nl = ch & 15; \
            size_t ga = (size_t)(n0 + nl) * 16384 + c * 2048 + (size_t)(k0 + hr) * 8; \
            cpa16(sbase + 20480 + hr * 272 + nl * 16, g_ah + ga); \
            cpa16(sbase + 29184 + hr * 272 + nl * 16, g_al + ga); \
        } }

    OLD(0, 0); CPCOMMIT();
    OLD(1, 1); CPCOMMIT();
    for (int kc = 0; kc < 8; kc++) {
        if (kc == 7) { CPWAIT(); } else { CPWAIT1(); }
        __syncthreads();
        if (kc < 6) { OLD((kc + 2) % 3, kc + 2); CPCOMMIT(); }
        mma_rArB(smem + (kc % 3) * 37888, wm, wn, acc);
    }

    EPI_TO_CS();
    const float* Cs = (const float*)smem;
    #pragma unroll
    for (int it = 0; it < 8; it++) {
        int p = tid + it * 256;
        int gr = p >> 4, nl = p & 15;
        int n = n0 + nl, bb = n >> 9, l = n & 511;
        float4 o1 = *(const float4*)(Cs + gr * 132 + nl * 8);
        float4 o2 = *(const float4*)(Cs + gr * 132 + nl * 8 + 4);
        size_t e = ((size_t)(bb * 8 + c) * 512 + l) * 2048 + (size_t)(g0 + gr) * 8;
        *(float4*)(out + e)     = o1;
        *(float4*)(out + e + 4) = o2;
    }
}

// ============================================================
extern "C" void kernel_launch(void* const* d_in, const int* in_sizes, int n_in,
                              void* d_out, int out_size) {
    const float* x    = (const float*)d_in[0];
    const float* prev = (const float*)d_in[1];
    const float* cw_q = (const float*)d_in[2];
    const float* cw_k = (const float*)d_in[3];
    const float* cw_v = (const float*)d_in[4];
    const float* wq   = (const float*)d_in[5];
    const float* wk   = (const float*)d_in[6];
    const float* wv   = (const float*)d_in[7];
    const float* wo   = (const float*)d_in[8];
    float* out    = (float*)d_out;
    float* qk_out = out + (size_t)NCF;

    cudaFuncSetAttribute(qkv_wm,  cudaFuncAttributeMaxDynamicSharedMemorySize, QKV_SMEM);
    cudaFuncSetAttribute(olin_wm, cudaFuncAttributeMaxDynamicSharedMemorySize, QKV_SMEM);
    cudaFuncSetAttribute(qk_wm,   cudaFuncAttributeMaxDynamicSharedMemorySize, QK_SMEM);
    cudaFuncSetAttribute(pv_wm,   cudaFuncAttributeMaxDynamicSharedMemorySize, PV_SMEM);

    prep_w<<<8192, 256>>>(wq, wk, wv, wo);
    conv3_kernel<<<dim3(1024, 4), 256>>>(x, cw_q, cw_k, cw_v);
    qkv_wm<<<dim3(64, 2, 24), 256, QKV_SMEM>>>();
    qk_wm<<<dim3(4, 4, 128), 256, QK_SMEM>>>(prev, qk_out);
    stats_kernel<<<65536, 128>>>(qk_out);
    pv_wm<<<dim3(2, 4, 128), 256, PV_SMEM>>>(qk_out);
    olin_wm<<<dim3(64, 2, 8), 256, QKV_SMEM>>>(out);
}

// round 9
// speedup vs baseline: 2.2476x; 1.0210x over previous
#include <cuda_runtime.h>
#include <cuda_bf16.h>
#include <mma.h>
#include <math.h>
#include <cstdint>

using namespace nvcuda;
typedef __nv_bfloat16 bf16;

#define C    8
#define L    512
#define NCF  (1024*8*2048)     // 16,777,216
#define LL   (512*512)

// ---- bf16 hi/lo scratch ----
__device__ bf16 g_c0h[NCF], g_c0l[NCF];
__device__ bf16 g_c1h[NCF], g_c1l[NCF];
__device__ bf16 g_c2h[NCF], g_c2l[NCF];
__device__ bf16 g_qh[NCF],  g_ql[NCF];
__device__ bf16 g_kh[NCF],  g_kl[NCF];
__device__ bf16 g_vh[NCF],  g_vl[NCF];
__device__ bf16 g_ah[NCF],  g_al[NCF];
__device__ bf16 g_ph[128*LL], g_pl[128*LL];   // exp'd softmax numerator, hi/lo
__device__ bf16 g_wh[4*C*65536], g_wl[4*C*65536];
__device__ float g_rsum[65536];

// ---- helpers ----
__device__ __forceinline__ uint32_t s2u(const void* p) {
    return (uint32_t)__cvta_generic_to_shared(p);
}
__device__ __forceinline__ void cpa16(uint32_t s, const void* g) {
    asm volatile("cp.async.cg.shared.global [%0], [%1], 16;" :: "r"(s), "l"(g));
}
#define CPCOMMIT() asm volatile("cp.async.commit_group;" ::: "memory")
#define CPWAIT()   asm volatile("cp.async.wait_group 0;" ::: "memory")
#define CPWAIT1()  asm volatile("cp.async.wait_group 1;" ::: "memory")

__device__ __forceinline__ void bsplit(float x, bf16& h, bf16& l) {
    h = __float2bfloat16(x);
    l = __float2bfloat16(x - __bfloat162float(h));
}
__device__ __forceinline__ uint32_t packbf2(bf16 a, bf16 b) {
    __nv_bfloat162 t; t.x = a; t.y = b;
    return *(uint32_t*)&t;
}
__device__ __forceinline__ void pack8(const float* v, uint4& H, uint4& Lo) {
    bf16 h[8], l[8];
    #pragma unroll
    for (int i = 0; i < 8; i++) bsplit(v[i], h[i], l[i]);
    H  = make_uint4(packbf2(h[0],h[1]), packbf2(h[2],h[3]), packbf2(h[4],h[5]), packbf2(h[6],h[7]));
    Lo = make_uint4(packbf2(l[0],l[1]), packbf2(l[2],l[3]), packbf2(l[4],l[5]), packbf2(l[6],l[7]));
}

typedef wmma::fragment<wmma::accumulator, 16, 16, 16, float> AccFrag;

// stage layouts (bytes), per stage:
//  qk  (40960): Qh 0  Ql 10240  Kh 20480  Kl 30720   [K-major 128x40, ldm 40]
//  qkv (37888): Wh 0  Wl 10240  ATh 20480 ATl 29184  [AT: 32x136, ldm 136]
//  pv  (37888): Ph 0  Pl 10240  Vh 20480  Vl 29184   [V: k x d, ldm 136]

// A row_major K-major (ldm 40); B col_major K-major (ldm 40)
__device__ __forceinline__ void mma_rAcB(const char* buf, int wm, int wn, AccFrag (&acc)[4][2]) {
    const bf16* Ah = (const bf16*)(buf);
    const bf16* Al = (const bf16*)(buf + 10240);
    const bf16* Bh = (const bf16*)(buf + 20480);
    const bf16* Bl = (const bf16*)(buf + 30720);
    #pragma unroll
    for (int ks = 0; ks < 2; ks++) {
        wmma::fragment<wmma::matrix_b, 16, 16, 16, bf16, wmma::col_major> bh[2], bl[2];
        #pragma unroll
        for (int j = 0; j < 2; j++) {
            int n_off = wn * 32 + j * 16;
            wmma::load_matrix_sync(bh[j], Bh + n_off * 40 + ks * 16, 40);
            wmma::load_matrix_sync(bl[j], Bl + n_off * 40 + ks * 16, 40);
        }
        #pragma unroll
        for (int i = 0; i < 4; i++) {
            int m_off = wm * 64 + i * 16;
            wmma::fragment<wmma::matrix_a, 16, 16, 16, bf16, wmma::row_major> ah, al;
            wmma::load_matrix_sync(ah, Ah + m_off * 40 + ks * 16, 40);
            wmma::load_matrix_sync(al, Al + m_off * 40 + ks * 16, 40);
            #pragma unroll
            for (int j = 0; j < 2; j++) {
                wmma::mma_sync(acc[i][j], ah, bh[j], acc[i][j]);
                wmma::mma_sync(acc[i][j], al, bh[j], acc[i][j]);
                wmma::mma_sync(acc[i][j], ah, bl[j], acc[i][j]);
            }
        }
    }
}

// A row_major K-major (ldm 40); B row_major [k][n] (ldm 136)
__device__ __forceinline__ void mma_rArB(const char* buf, int wm, int wn, AccFrag (&acc)[4][2]) {
    const bf16* Ah = (const bf16*)(buf);
    const bf16* Al = (const bf16*)(buf + 10240);
    const bf16* Bh = (const bf16*)(buf + 20480);
    const bf16* Bl = (const bf16*)(buf + 29184);
    #pragma unroll
    for (int ks = 0; ks < 2; ks++) {
        wmma::fragment<wmma::matrix_b, 16, 16, 16, bf16, wmma::row_major> bh[2], bl[2];
        #pragma unroll
        for (int j = 0; j < 2; j++) {
            int n_off = wn * 32 + j * 16;
            wmma::load_matrix_sync(bh[j], Bh + (ks * 16) * 136 + n_off, 136);
            wmma::load_matrix_sync(bl[j], Bl + (ks * 16) * 136 + n_off, 136);
        }
        #pragma unroll
        for (int i = 0; i < 4; i++) {
            int m_off = wm * 64 + i * 16;
            wmma::fragment<wmma::matrix_a, 16, 16, 16, bf16, wmma::row_major> ah, al;
            wmma::load_matrix_sync(ah, Ah + m_off * 40 + ks * 16, 40);
            wmma::load_matrix_sync(al, Al + m_off * 40 + ks * 16, 40);
            #pragma unroll
            for (int j = 0; j < 2; j++) {
                wmma::mma_sync(acc[i][j], ah, bh[j], acc[i][j]);
                wmma::mma_sync(acc[i][j], al, bh[j], acc[i][j]);
                wmma::mma_sync(acc[i][j], ah, bl[j], acc[i][j]);
            }
        }
    }
}

#define DECL_ACC() \
    AccFrag acc[4][2]; \
    _Pragma("unroll") for (int i_ = 0; i_ < 4; i_++) \
        _Pragma("unroll") for (int j_ = 0; j_ < 2; j_++) wmma::fill_fragment(acc[i_][j_], 0.0f);

#define EPI_TO_CS() \
    __syncthreads(); \
    { float* Cs_ = (float*)smem; \
      _Pragma("unroll") for (int i_ = 0; i_ < 4; i_++) \
        _Pragma("unroll") for (int j_ = 0; j_ < 2; j_++) \
          wmma::store_matrix_sync(Cs_ + (wm*64 + i_*16)*132 + wn*32 + j_*16, acc[i_][j_], 132, wmma::mem_row_major); } \
    __syncthreads();

// ============================================================
// prep_w: split 4 weight tensors to bf16 hi/lo.  grid 8192 x 256.
// ============================================================
__global__ void prep_w(const float* __restrict__ wq, const float* __restrict__ wk,
                       const float* __restrict__ wv, const float* __restrict__ wo) {
    int idx = blockIdx.x * 256 + threadIdx.x;
    int t = idx >> 19, off = idx & 524287;
    const float* src = (t == 0) ? wq : (t == 1) ? wk : (t == 2) ? wv : wo;
    bf16 h, l;
    bsplit(src[off], h, l);
    g_wh[idx] = h; g_wl[idx] = l;
}

// ============================================================
// conv3: fused 3x conv3x3 -> bf16 hi/lo outputs [n][c][h*8+w]
// ============================================================
__global__ void conv3_kernel(const float* __restrict__ x,
                             const float* __restrict__ wq,
                             const float* __restrict__ wk,
                             const float* __restrict__ wv) {
    __shared__ float xt[8*66*10];
    __shared__ float wsm[3*576];
    const int n  = blockIdx.x;
    const int y0 = blockIdx.y * 64;
    const int b  = n >> 9, l = n & 511;
    const int tid = threadIdx.x;

    for (int i = tid; i < 576; i += 256) {
        wsm[i] = wq[i]; wsm[576 + i] = wk[i]; wsm[1152 + i] = wv[i];
    }
    for (int i = tid; i < 8*66*10; i += 256) {
        int ci = i / 660, rem = i % 660;
        int yy = rem / 10, xx = rem % 10;
        int y = y0 + yy - 1, xc = xx - 1;
        float v = 0.f;
        if (y >= 0 && y < 256 && xc >= 0 && xc < 8)
            v = x[(((size_t)(b*C + ci)*L + l)*256 + y)*8 + xc];
        xt[i] = v;
    }
    __syncthreads();

    const int yb = tid >> 3, w = tid & 7;
    float acc[2][24];
    #pragma unroll
    for (int r = 0; r < 2; r++)
        #pragma unroll
        for (int o = 0; o < 24; o++) acc[r][o] = 0.f;

    for (int ci = 0; ci < 8; ci++) {
        float xv[2][9];
        #pragma unroll
        for (int r = 0; r < 2; r++)
            #pragma unroll
            for (int ky = 0; ky < 3; ky++)
                #pragma unroll
                for (int kx = 0; kx < 3; kx++)
                    xv[r][ky*3 + kx] = xt[ci*660 + (yb + r*32 + ky)*10 + (w + kx)];
        #pragma unroll
        for (int o = 0; o < 24; o++) {
            int p = o >> 3, co = o & 7;
            const float* wp = &wsm[p*576 + (co*8 + ci)*9];
            #pragma unroll
            for (int k9 = 0; k9 < 9; k9++) {
                float ww = wp[k9];
                acc[0][o] += xv[0][k9] * ww;
                acc[1][o] += xv[1][k9] * ww;
            }
        }
    }
    #pragma unroll
    for (int p = 0; p < 3; p++) {
        bf16* oh = (p == 0) ? g_c0h : (p == 1) ? g_c1h : g_c2h;
        bf16* ol = (p == 0) ? g_c0l : (p == 1) ? g_c1l : g_c2l;
        #pragma unroll
        for (int co = 0; co < 8; co++)
            #pragma unroll
            for (int r = 0; r < 2; r++) {
                size_t off = (size_t)n*16384 + co*2048 + (size_t)(y0 + yb + r*32)*8 + w;
                bf16 hh, lv;
                bsplit(acc[r][p*8 + co], hh, lv);
                oh[off] = hh; ol[off] = lv;
            }
    }
}

// ============================================================
// qkv_wm: 3 projections, transposed: outT[g][m] = W[g][:].AT[:][m]
// 3-stage cp.async pipeline. RoPE fused in epilogue.
// grid (64, 2, 24), block 256, 2 CTAs/SM.
// ============================================================
#define QKV_SMEM 113664
__global__ void __launch_bounds__(256, 2)
qkv_wm() {
    extern __shared__ __align__(16) char smem[];
    const uint32_t sb = s2u(smem);
    const int tid = threadIdx.x, wid = tid >> 5;
    const int wm = wid >> 2, wn = wid & 3;
    const int c = blockIdx.z & 7, proj = blockIdx.z >> 3;
    const int m0 = blockIdx.x * 128, g0 = blockIdx.y * 128, n0 = m0 >> 3;
    const bf16* Ah_g = (proj == 0) ? g_c0h : (proj == 1) ? g_c1h : g_c2h;
    const bf16* Al_g = (proj == 0) ? g_c0l : (proj == 1) ? g_c1l : g_c2l;
    const bf16* Wh_g = g_wh + (size_t)proj * 524288;
    const bf16* Wl_g = g_wl + (size_t)proj * 524288;
    bf16* Oh = (proj == 0) ? g_qh : (proj == 1) ? g_kh : g_vh;
    bf16* Ol = (proj == 0) ? g_ql : (proj == 1) ? g_kl : g_vl;

    DECL_ACC();

    #define QKVLD(s, kc) { \
        uint32_t sbase = sb + (s) * 37888; int k0 = (kc) * 32; \
        _Pragma("unroll") for (int i = 0; i < 2; i++) { \
            int ch = tid + i * 256; \
            int gr = ch >> 2, c4 = ch & 3; \
            size_t gb = (size_t)c * 65536 + (size_t)(g0 + gr) * 256 + k0 + c4 * 8; \
            cpa16(sbase + gr * 80 + c4 * 16,         Wh_g + gb); \
            cpa16(sbase + 10240 + gr * 80 + c4 * 16, Wl_g + gb); \
            int hr = ch >> 4, nl = ch & 15; \
            size_t ga = (size_t)(n0 + nl) * 16384 + c * 2048 + (size_t)(k0 + hr) * 8; \
            cpa16(sbase + 20480 + hr * 272 + nl * 16, Ah_g + ga); \
            cpa16(sbase + 29184 + hr * 272 + nl * 16, Al_g + ga); \
        } }

    QKVLD(0, 0); CPCOMMIT();
    QKVLD(1, 1); CPCOMMIT();
    for (int kc = 0; kc < 8; kc++) {
        if (kc == 7) { CPWAIT(); } else { CPWAIT1(); }
        __syncthreads();
        if (kc < 6) { QKVLD((kc + 2) % 3, kc + 2); CPCOMMIT(); }
        mma_rArB(smem + (kc % 3) * 37888, wm, wn, acc);
    }

    // Cs holds outT: row = g_rel, col = m_rel = (n-n0)*8 + w
    EPI_TO_CS();
    const float* Cs = (const float*)smem;
    #pragma unroll
    for (int it = 0; it < 8; it++) {
        int p = tid + it * 256;
        int gr = p >> 4, nl = p & 15;
        const float* src = Cs + gr * 132 + nl * 8;
        float4 v01 = *(const float4*)(src);
        float4 v23 = *(const float4*)(src + 4);
        float v[8] = {v01.x, v01.y, v01.z, v01.w, v23.x, v23.y, v23.z, v23.w};
        // fused RoPE: q/k projections, head-dims d = (g&31)*8 + w < 32
        int g = g0 + gr;
        if (proj < 2 && (g & 31) < 4) {
            int l = (n0 + nl) & 511;
            int jb = (g & 31) * 4;
            #pragma unroll
            for (int t = 0; t < 4; t++) {
                float invf = exp2f(-(float)(jb + t) * (13.287712379549449f / 16.0f));
                float sn, cn;
                sincosf((float)l * invf, &sn, &cn);
                float a = v[2*t], bq = v[2*t+1];
                v[2*t]   = a * cn - bq * sn;
                v[2*t+1] = bq * cn + a * sn;
            }
        }
        uint4 H, Lo;
        pack8(v, H, Lo);
        size_t e = (size_t)(n0 + nl) * 16384 + (size_t)c * 2048 + (size_t)g * 8;
        *(uint4*)(Oh + e) = H;
        *(uint4*)(Ol + e) = Lo;
    }
}

// ============================================================
// qk_wm: 2-stage pipeline, vectorized epilogue.
// grid (4, 4, 128), block 256, 2 CTAs/SM.
// ============================================================
#define QK_SMEM 81920
__global__ void __launch_bounds__(256, 2)
qk_wm(const float* __restrict__ prev, float* __restrict__ qk) {
    extern __shared__ __align__(16) char smem[];
    const uint32_t sb = s2u(smem);
    const int tid = threadIdx.x, wid = tid >> 5;
    const int wm = wid >> 2, wn = wid & 3;
    const int z = blockIdx.z;
    const int b = z >> 6, c = (z >> 3) & 7, nh = z & 7;
    const int l0 = blockIdx.y * 128, m0 = blockIdx.x * 128;
    const size_t coff = (size_t)c * 2048 + nh * 256;
    const size_t bL = (size_t)b * 512;

    DECL_ACC();

    #define QKLD(s, kc) { \
        uint32_t sbase = sb + (s) * 40960; int k0 = (kc) * 32; \
        _Pragma("unroll") for (int i = 0; i < 2; i++) { \
            int ch = tid + i * 256; \
            int r = ch >> 2, c4 = ch & 3; \
            uint32_t so = r * 80 + c4 * 16; \
            size_t ga = (bL + l0 + r) * 16384 + coff + k0 + c4 * 8; \
            size_t gb = (bL + m0 + r) * 16384 + coff + k0 + c4 * 8; \
            cpa16(sbase + so,         g_qh + ga); \
            cpa16(sbase + 10240 + so, g_ql + ga); \
            cpa16(sbase + 20480 + so, g_kh + gb); \
            cpa16(sbase + 30720 + so, g_kl + gb); \
        } }

    QKLD(0, 0); CPCOMMIT();
    for (int kc = 0; kc < 8; kc++) {
        CPWAIT(); __syncthreads();
        if (kc < 7) { QKLD((kc + 1) & 1, kc + 1); CPCOMMIT(); }
        mma_rAcB(smem + (kc & 1) * 40960, wm, wn, acc);
    }

    EPI_TO_CS();
    const float* Cs = (const float*)smem;
    const int col4 = (tid & 31) * 4;
    const int rb = tid >> 5;
    #pragma unroll
    for (int jj = 0; jj < 16; jj++) {
        int r = rb + jj * 8;
        float4 cv = *(const float4*)(Cs + r * 132 + col4);
        size_t idx = (size_t)z * LL + (size_t)(l0 + r) * 512 + m0 + col4;
        float4 pv = *(const float4*)(prev + idx);
        float4 o;
        o.x = cv.x * 0.0625f + pv.x;
        o.y = cv.y * 0.0625f + pv.y;
        o.z = cv.z * 0.0625f + pv.z;
        o.w = cv.w * 0.0625f + pv.w;
        *(float4*)(qk + idx) = o;
    }
}

// ============================================================
// stats: per-row max + sumexp AND write exp'd P as hi/lo bf16.
// grid 65536 x 128.
// ============================================================
__global__ void stats_kernel(const float* __restrict__ qk) {
    const int row = blockIdx.x;
    const int tid = threadIdx.x;
    const float4 v = reinterpret_cast<const float4*>(qk + (size_t)row*512)[tid];
    float mx = fmaxf(fmaxf(v.x, v.y), fmaxf(v.z, v.w));
    #pragma unroll
    for (int o = 16; o; o >>= 1) mx = fmaxf(mx, __shfl_xor_sync(~0u, mx, o));
    __shared__ float sm[4], ss[4];
    if ((tid & 31) == 0) sm[tid >> 5] = mx;
    __syncthreads();
    mx = fmaxf(fmaxf(sm[0], sm[1]), fmaxf(sm[2], sm[3]));
    float e0 = expf(v.x - mx), e1 = expf(v.y - mx);
    float e2 = expf(v.z - mx), e3 = expf(v.w - mx);
    // write P hi/lo
    bf16 h0, l0, h1, l1, h2, l2, h3, l3;
    bsplit(e0, h0, l0); bsplit(e1, h1, l1);
    bsplit(e2, h2, l2); bsplit(e3, h3, l3);
    size_t pidx = (size_t)row * 512 + tid * 4;
    *(uint2*)(g_ph + pidx) = make_uint2(packbf2(h0, h1), packbf2(h2, h3));
    *(uint2*)(g_pl + pidx) = make_uint2(packbf2(l0, l1), packbf2(l2, l3));
    float s = e0 + e1 + e2 + e3;
    #pragma unroll
    for (int o = 16; o; o >>= 1) s += __shfl_xor_sync(~0u, s, o);
    if ((tid & 31) == 0) ss[tid >> 5] = s;
    __syncthreads();
    if (tid == 0)
        g_rsum[row] = ss[0] + ss[1] + ss[2] + ss[3];
}

// ============================================================
// pv_wm: pure 3-stage cp.async GEMM (P hi/lo from stats, V hi/lo).
// grid (2, 4, 128), block 256, 2 CTAs/SM. K=512, 16 chunks.
// ============================================================
#define PV_SMEM 114688
__global__ void __launch_bounds__(256, 2)
pv_wm() {
    extern __shared__ __align__(16) char smem[];
    const uint32_t sb = s2u(smem);
    const int tid = threadIdx.x, wid = tid >> 5;
    const int wm = wid >> 2, wn = wid & 3;
    const int z = blockIdx.z;
    const int b = z >> 6, c = (z >> 3) & 7, nh = z & 7;
    const int l0 = blockIdx.y * 128, d0 = blockIdx.x * 128;
    const size_t coff = (size_t)c * 2048 + nh * 256;
    const size_t bL = (size_t)b * 512;
    float* rinv = (float*)(smem + 113664);
    if (tid < 128) rinv[tid] = 1.0f / g_rsum[z * 512 + l0 + tid];

    DECL_ACC();

    #define PVLD(s, kc) { \
        uint32_t sbase = sb + (s) * 37888; int k0 = (kc) * 32; \
        _Pragma("unroll") for (int i = 0; i < 2; i++) { \
            int ch = tid + i * 256; \
            int r = ch >> 2, c4 = ch & 3; \
            size_t gp = (size_t)z * LL + (size_t)(l0 + r) * 512 + k0 + c4 * 8; \
            cpa16(sbase + r * 80 + c4 * 16,         g_ph + gp); \
            cpa16(sbase + 10240 + r * 80 + c4 * 16, g_pl + gp); \
            int mr = ch >> 4, d8 = ch & 15; \
            size_t gv = (bL + k0 + mr) * 16384 + coff + d0 + d8 * 8; \
            cpa16(sbase + 20480 + mr * 272 + d8 * 16, g_vh + gv); \
            cpa16(sbase + 29184 + mr * 272 + d8 * 16, g_vl + gv); \
        } }

    PVLD(0, 0); CPCOMMIT();
    PVLD(1, 1); CPCOMMIT();
    for (int kc = 0; kc < 16; kc++) {
        if (kc == 15) { CPWAIT(); } else { CPWAIT1(); }
        __syncthreads();
        if (kc < 14) { PVLD((kc + 2) % 3, kc + 2); CPCOMMIT(); }
        mma_rArB(smem + (kc % 3) * 37888, wm, wn, acc);
    }

    EPI_TO_CS();
    const float* Cs = (const float*)smem;
    #pragma unroll
    for (int it = 0; it < 8; it++) {
        int r = (tid >> 4) + it * 16;
        int col8 = (tid & 15) * 8;
        float4 a1 = *(const float4*)(Cs + r * 132 + col8);
        float4 a2 = *(const float4*)(Cs + r * 132 + col8 + 4);
        float iv = rinv[r];
        float v[8] = {a1.x*iv, a1.y*iv, a1.z*iv, a1.w*iv, a2.x*iv, a2.y*iv, a2.z*iv, a2.w*iv};
        uint4 H, Lo;
        pack8(v, H, Lo);
        size_t e = (bL + l0 + r) * 16384 + coff + d0 + col8;
        *(uint4*)(g_ah + e) = H;
        *(uint4*)(g_al + e) = Lo;
    }
}

// ============================================================
// olin_wm: wo projection, transposed, 3-stage pipeline. -> f32 out.
// ============================================================
__global__ void __launch_bounds__(256, 2)
olin_wm(float* __restrict__ out) {
    extern __shared__ __align__(16) char smem[];
    const uint32_t sb = s2u(smem);
    const int tid = threadIdx.x, wid = tid >> 5;
    const int wm = wid >> 2, wn = wid & 3;
    const int c = blockIdx.z, m0 = blockIdx.x * 128, g0 = blockIdx.y * 128, n0 = m0 >> 3;
    const bf16* Wh_g = g_wh + (size_t)3 * 524288;
    const bf16* Wl_g = g_wl + (size_t)3 * 524288;

    DECL_ACC();

    #define OLD(s, kc) { \
        uint32_t sbase = sb + (s) * 37888; int k0 = (kc) * 32; \
        _Pragma("unroll") for (int i = 0; i < 2; i++) { \
            int ch = tid + i * 256; \
            int gr = ch >> 2, c4 = ch & 3; \
            size_t gb = (size_t)c * 65536 + (size_t)(g0 + gr) * 256 + k0 + c4 * 8; \
            cpa16(sbase + gr * 80 + c4 * 16,         Wh_g + gb); \
            cpa16(sbase + 10240 + gr * 80 + c4 * 16, Wl_g + gb); \
            int hr = ch >> 4, nl = ch & 15; \
            size_t ga = (size_t)(n0 + nl) * 16384 + c * 2048 + (size_t)(k0 + hr) * 8; \
            cpa16(sbase + 20480 + hr * 272 + nl * 16, g_ah + ga); \
            cpa16(sbase + 29184 + hr * 272 + nl * 16, g_al + ga); \
        } }

    OLD(0, 0); CPCOMMIT();
    OLD(1, 1); CPCOMMIT();
    for (int kc = 0; kc < 8; kc++) {
        if (kc == 7) { CPWAIT(); } else { CPWAIT1(); }
        __syncthreads();
        if (kc < 6) { OLD((kc + 2) % 3, kc + 2); CPCOMMIT(); }
        mma_rArB(smem + (kc % 3) * 37888, wm, wn, acc);
    }

    EPI_TO_CS();
    const float* Cs = (const float*)smem;
    #pragma unroll
    for (int it = 0; it < 8; it++) {
        int p = tid + it * 256;
        int gr = p >> 4, nl = p & 15;
        int n = n0 + nl, bb = n >> 9, l = n & 511;
        float4 o1 = *(const float4*)(Cs + gr * 132 + nl * 8);
        float4 o2 = *(const float4*)(Cs + gr * 132 + nl * 8 + 4);
        size_t e = ((size_t)(bb * 8 + c) * 512 + l) * 2048 + (size_t)(g0 + gr) * 8;
        *(float4*)(out + e)     = o1;
        *(float4*)(out + e + 4) = o2;
    }
}

// ============================================================
extern "C" void kernel_launch(void* const* d_in, const int* in_sizes, int n_in,
                              void* d_out, int out_size) {
    const float* x    = (const float*)d_in[0];
    const float* prev = (const float*)d_in[1];
    const float* cw_q = (const float*)d_in[2];
    const float* cw_k = (const float*)d_in[3];
    const float* cw_v = (const float*)d_in[4];
    const float* wq   = (const float*)d_in[5];
    const float* wk   = (const float*)d_in[6];
    const float* wv   = (const float*)d_in[7];
    const float* wo   = (const float*)d_in[8];
    float* out    = (float*)d_out;
    float* qk_out = out + (size_t)NCF;

    cudaFuncSetAttribute(qkv_wm,  cudaFuncAttributeMaxDynamicSharedMemorySize, QKV_SMEM);
    cudaFuncSetAttribute(olin_wm, cudaFuncAttributeMaxDynamicSharedMemorySize, QKV_SMEM);
    cudaFuncSetAttribute(qk_wm,   cudaFuncAttributeMaxDynamicSharedMemorySize, QK_SMEM);
    cudaFuncSetAttribute(pv_wm,   cudaFuncAttributeMaxDynamicSharedMemorySize, PV_SMEM);

    prep_w<<<8192, 256>>>(wq, wk, wv, wo);
    conv3_kernel<<<dim3(1024, 4), 256>>>(x, cw_q, cw_k, cw_v);
    qkv_wm<<<dim3(64, 2, 24), 256, QKV_SMEM>>>();
    qk_wm<<<dim3(4, 4, 128), 256, QK_SMEM>>>(prev, qk_out);
    stats_kernel<<<65536, 128>>>(qk_out);
    pv_wm<<<dim3(2, 4, 128), 256, PV_SMEM>>>();
    olin_wm<<<dim3(64, 2, 8), 256, QKV_SMEM>>>(out);
}